// round 1
// baseline (speedup 1.0000x reference)
#include <cuda_runtime.h>

#define NP   100000
#define CCH  64
#define KK   27
#define EPSV 1e-5f
#define TILE 64
#define NBLK ((NP + TILE - 1) / TILE)   // 1563
#define PAD  68                          // row stride in floats (16B-aligned, conflict-skewed)

// ---------------- scratch (device globals; no allocation allowed) ----------------
__device__ float g_buf1[NP * CCH];
__device__ float g_buf2[NP * CCH];
__device__ float g_part1[NBLK * 2 * CCH];
__device__ float g_part2[NBLK * 2 * CCH];
__device__ float g_stats1[2 * CCH];   // [0:64) scale, [64:128) shift
__device__ float g_stats2[2 * CCH];

// ---------------------------------------------------------------------------
// Sparse conv: dst[n,d] = sum_k sum_c g[k,n,c] * W[k,c,d]
//   g[k,n,c] = T(src[idx[k,n], c]) * mask[k,n]
//   T = identity (BN_IN=false) or relu(x*scale + shift) (BN_IN=true, BN1+ReLU fused)
// Also emits deterministic per-block per-channel (sum, sumsq) partials for BN stats.
// ---------------------------------------------------------------------------
template <bool BN_IN>
__global__ __launch_bounds__(256, 4)
void conv_kernel(const float* __restrict__ src,
                 const int*   __restrict__ idx,
                 const float* __restrict__ mask,
                 const float* __restrict__ W,
                 const float* __restrict__ stats_in,
                 float*       __restrict__ dst,
                 float*       __restrict__ part)
{
    __shared__ float Gs[TILE][PAD];
    __shared__ float Ws[TILE][PAD];
    __shared__ int   s_idx[TILE];
    __shared__ float s_msk[TILE];
    __shared__ float s_scale[CCH];
    __shared__ float s_shift[CCH];
    __shared__ float s_red1[4][CCH];
    __shared__ float s_red2[4][CCH];

    const int tid = threadIdx.x;
    const int n0  = blockIdx.x * TILE;
    const int ty4 = (tid >> 4) * 4;
    const int tx4 = (tid & 15) * 4;

    if (BN_IN && tid < CCH) {
        s_scale[tid] = stats_in[tid];
        s_shift[tid] = stats_in[CCH + tid];
    }

    float acc[4][4];
#pragma unroll
    for (int i = 0; i < 4; ++i)
#pragma unroll
        for (int j = 0; j < 4; ++j) acc[i][j] = 0.f;

    for (int k = 0; k < KK; ++k) {
        __syncthreads();   // previous compute done; Gs/Ws/s_idx reusable

        if (tid < TILE) {
            int n = n0 + tid;
            if (n < NP) {
                s_idx[tid] = idx[k * NP + n];
                s_msk[tid] = mask[k * NP + n];
            } else {
                s_idx[tid] = 0;
                s_msk[tid] = 0.f;
            }
        }
        // W[k] tile: [c][d], 64x64 floats, float4 per thread x4
        {
            const float4* Wk = (const float4*)(W + (size_t)k * CCH * CCH);
#pragma unroll
            for (int p = 0; p < 4; ++p) {
                int r  = p * 16 + (tid >> 4);
                int q  = (tid & 15);
                float4 w = Wk[r * 16 + q];
                *(float4*)&Ws[r][q * 4] = w;
            }
        }
        __syncthreads();   // s_idx ready

        // gather (masked, optionally BN1+ReLU transformed)
#pragma unroll
        for (int p = 0; p < 4; ++p) {
            int r  = p * 16 + (tid >> 4);
            int c4 = (tid & 15) * 4;
            float m = s_msk[r];
            float4 v = make_float4(0.f, 0.f, 0.f, 0.f);
            if (m != 0.f) {
                v = *(const float4*)(src + (size_t)s_idx[r] * CCH + c4);
                if (BN_IN) {
                    v.x = fmaxf(fmaf(v.x, s_scale[c4 + 0], s_shift[c4 + 0]), 0.f);
                    v.y = fmaxf(fmaf(v.y, s_scale[c4 + 1], s_shift[c4 + 1]), 0.f);
                    v.z = fmaxf(fmaf(v.z, s_scale[c4 + 2], s_shift[c4 + 2]), 0.f);
                    v.w = fmaxf(fmaf(v.w, s_scale[c4 + 3], s_shift[c4 + 3]), 0.f);
                }
                v.x *= m; v.y *= m; v.z *= m; v.w *= m;
            }
            *(float4*)&Gs[r][c4] = v;
        }
        __syncthreads();   // Gs + Ws ready

#pragma unroll 16
        for (int c = 0; c < CCH; ++c) {
            float a0 = Gs[ty4 + 0][c];
            float a1 = Gs[ty4 + 1][c];
            float a2 = Gs[ty4 + 2][c];
            float a3 = Gs[ty4 + 3][c];
            float4 b = *(const float4*)&Ws[c][tx4];
            acc[0][0] = fmaf(a0, b.x, acc[0][0]);
            acc[0][1] = fmaf(a0, b.y, acc[0][1]);
            acc[0][2] = fmaf(a0, b.z, acc[0][2]);
            acc[0][3] = fmaf(a0, b.w, acc[0][3]);
            acc[1][0] = fmaf(a1, b.x, acc[1][0]);
            acc[1][1] = fmaf(a1, b.y, acc[1][1]);
            acc[1][2] = fmaf(a1, b.z, acc[1][2]);
            acc[1][3] = fmaf(a1, b.w, acc[1][3]);
            acc[2][0] = fmaf(a2, b.x, acc[2][0]);
            acc[2][1] = fmaf(a2, b.y, acc[2][1]);
            acc[2][2] = fmaf(a2, b.z, acc[2][2]);
            acc[2][3] = fmaf(a2, b.w, acc[2][3]);
            acc[3][0] = fmaf(a3, b.x, acc[3][0]);
            acc[3][1] = fmaf(a3, b.y, acc[3][1]);
            acc[3][2] = fmaf(a3, b.z, acc[3][2]);
            acc[3][3] = fmaf(a3, b.w, acc[3][3]);
        }
    }

    // ---- epilogue: write tile + deterministic per-channel partial stats ----
    __syncthreads();   // compute done; Gs reusable as output staging
#pragma unroll
    for (int i = 0; i < 4; ++i) {
        int r = ty4 + i;
        float4 o = make_float4(acc[i][0], acc[i][1], acc[i][2], acc[i][3]);
        *(float4*)&Gs[r][tx4] = o;
        int n = n0 + r;
        if (n < NP)
            *(float4*)(dst + (size_t)n * CCH + tx4) = o;
    }
    __syncthreads();
    {
        int c = tid & 63;
        int g = tid >> 6;
        float s = 0.f, s2 = 0.f;
#pragma unroll
        for (int r = 0; r < 16; ++r) {
            float v = Gs[g * 16 + r][c];   // rows >= N are exact zeros -> contribute 0
            s += v;
            s2 = fmaf(v, v, s2);
        }
        s_red1[g][c] = s;
        s_red2[g][c] = s2;
    }
    __syncthreads();
    if (tid < CCH) {
        float s  = s_red1[0][tid] + s_red1[1][tid] + s_red1[2][tid] + s_red1[3][tid];
        float s2 = s_red2[0][tid] + s_red2[1][tid] + s_red2[2][tid] + s_red2[3][tid];
        part[blockIdx.x * (2 * CCH) + tid]       = s;
        part[blockIdx.x * (2 * CCH) + CCH + tid] = s2;
    }
}

// ---------------------------------------------------------------------------
// Per-channel stats finalize: scale = gamma * rsqrt(var + eps), shift = beta - mean*scale
// Deterministic (fixed strided partition + fixed-order tree reduce).
// ---------------------------------------------------------------------------
__global__ __launch_bounds__(256)
void finalize_kernel(const float* __restrict__ part,
                     const float* __restrict__ gamma,
                     const float* __restrict__ beta,
                     float*       __restrict__ stats)
{
    const int c   = blockIdx.x;
    const int tid = threadIdx.x;
    float s = 0.f, s2 = 0.f;
    for (int b = tid; b < NBLK; b += 256) {
        s  += part[b * (2 * CCH) + c];
        s2 += part[b * (2 * CCH) + CCH + c];
    }
    __shared__ float r1[256], r2[256];
    r1[tid] = s; r2[tid] = s2;
    __syncthreads();
    for (int o = 128; o > 0; o >>= 1) {
        if (tid < o) { r1[tid] += r1[tid + o]; r2[tid] += r2[tid + o]; }
        __syncthreads();
    }
    if (tid == 0) {
        float mean = r1[0] * (1.0f / NP);
        float var  = r2[0] * (1.0f / NP) - mean * mean;
        float istd = rsqrtf(var + EPSV);
        float sc   = istd * gamma[c];
        stats[c]        = sc;
        stats[CCH + c]  = beta[c] - mean * sc;
    }
}

// ---------------------------------------------------------------------------
// out = relu( buf2*scale2 + shift2 + feats )
// ---------------------------------------------------------------------------
__global__ __launch_bounds__(256)
void epi_kernel(const float* __restrict__ buf2,
                const float* __restrict__ stats,
                const float* __restrict__ feats,
                float*       __restrict__ out)
{
    __shared__ float sc[CCH], sh[CCH];
    if (threadIdx.x < CCH) {
        sc[threadIdx.x] = stats[threadIdx.x];
        sh[threadIdx.x] = stats[CCH + threadIdx.x];
    }
    __syncthreads();
    int i = blockIdx.x * blockDim.x + threadIdx.x;   // float4 index
    if (i < NP * CCH / 4) {
        float4 v = ((const float4*)buf2)[i];
        float4 f = ((const float4*)feats)[i];
        int c = (i * 4) & 63;
        v.x = fmaxf(fmaf(v.x, sc[c + 0], sh[c + 0]) + f.x, 0.f);
        v.y = fmaxf(fmaf(v.y, sc[c + 1], sh[c + 1]) + f.y, 0.f);
        v.z = fmaxf(fmaf(v.z, sc[c + 2], sh[c + 2]) + f.z, 0.f);
        v.w = fmaxf(fmaf(v.w, sc[c + 3], sh[c + 3]) + f.w, 0.f);
        ((float4*)out)[i] = v;
    }
}

// ---------------------------------------------------------------------------
extern "C" void kernel_launch(void* const* d_in, const int* in_sizes, int n_in,
                              void* d_out, int out_size)
{
    const float* feats  = (const float*)d_in[0];
    const float* W1     = (const float*)d_in[1];
    const float* gamma1 = (const float*)d_in[2];
    const float* beta1  = (const float*)d_in[3];
    const float* W2     = (const float*)d_in[4];
    const float* gamma2 = (const float*)d_in[5];
    const float* beta2  = (const float*)d_in[6];
    const int*   idx1   = (const int*)  d_in[7];
    const float* mask1  = (const float*)d_in[8];
    const int*   idx2   = (const int*)  d_in[9];
    const float* mask2  = (const float*)d_in[10];
    float* out = (float*)d_out;

    float *buf1, *buf2, *part1, *part2, *st1, *st2;
    cudaGetSymbolAddress((void**)&buf1,  g_buf1);
    cudaGetSymbolAddress((void**)&buf2,  g_buf2);
    cudaGetSymbolAddress((void**)&part1, g_part1);
    cudaGetSymbolAddress((void**)&part2, g_part2);
    cudaGetSymbolAddress((void**)&st1,   g_stats1);
    cudaGetSymbolAddress((void**)&st2,   g_stats2);

    conv_kernel<false><<<NBLK, 256>>>(feats, idx1, mask1, W1, nullptr, buf1, part1);
    finalize_kernel<<<CCH, 256>>>(part1, gamma1, beta1, st1);
    conv_kernel<true><<<NBLK, 256>>>(buf1, idx2, mask2, W2, st1, buf2, part2);
    finalize_kernel<<<CCH, 256>>>(part2, gamma2, beta2, st2);

    int epi_blocks = (NP * CCH / 4 + 255) / 256;
    epi_kernel<<<epi_blocks, 256>>>(buf2, st2, feats, out);
}

// round 4
// speedup vs baseline: 1.2256x; 1.2256x over previous
#include <cuda_runtime.h>
#include <cstdint>

#define NP     100000
#define CCH    64
#define KK     27
#define EPSV   1e-5f
#define TILE_M 128
#define NB2    ((NP + TILE_M - 1) / TILE_M)   // 782
#define GSTR   68
#define WSTR   68

// ---------------- scratch (device globals; no allocation allowed) ----------------
__device__ float g_buf1[NP * CCH];
__device__ float g_buf2[NP * CCH];
__device__ float g_part1[NB2 * 2 * CCH];
__device__ float g_part2[NB2 * 2 * CCH];
__device__ float g_stats1[2 * CCH];   // [0:64) scale, [64:128) shift
__device__ float g_stats2[2 * CCH];

// ---------------- helpers ----------------
__device__ __forceinline__ uint32_t tf32r(float x) {
    uint32_t u;
    asm("cvt.rna.tf32.f32 %0, %1;" : "=r"(u) : "f"(x));
    return u;
}

// D += A(16x8) * B(8x8), tf32 inputs, fp32 accum (sm_80+ portable PTX)
__device__ __forceinline__ void mma8(float* d, const uint32_t* a, const uint32_t* b) {
    asm volatile(
        "mma.sync.aligned.m16n8k8.row.col.f32.tf32.tf32.f32 "
        "{%0,%1,%2,%3}, {%4,%5,%6,%7}, {%8,%9}, {%0,%1,%2,%3};"
        : "+f"(d[0]), "+f"(d[1]), "+f"(d[2]), "+f"(d[3])
        : "r"(a[0]), "r"(a[1]), "r"(a[2]), "r"(a[3]), "r"(b[0]), "r"(b[1]));
}

// SMEM: G[128][GSTR] | Wm[64][WSTR] | SC[128] | RED[512]
#define SMEM_FLOATS (128 * GSTR + 64 * WSTR + 128 + 512)
#define SMEM_BYTES  (SMEM_FLOATS * 4)

// ---------------------------------------------------------------------------
// Sparse conv via mma.sync tf32, with fused deterministic BN-stat partials.
//   dst[n,d] = sum_k sum_c T(src[idx[k,n],c]) * mask[k,n] * W[k,c,d]
//   T = identity, or relu(x*scale + shift) when BN_IN (BN1+ReLU fused into gather)
// ---------------------------------------------------------------------------
template <bool BN_IN>
__global__ __launch_bounds__(256, 2)
void conv_mma(const float* __restrict__ src,
              const int*   __restrict__ idx,
              const float* __restrict__ mask,
              const float* __restrict__ W,
              const float* __restrict__ stats_in,
              float*       __restrict__ dst,
              float*       __restrict__ part)
{
    extern __shared__ float sm[];
    float* G   = sm;                        // gathered A tile, 128 x 64 (stride 68)
    float* Wm  = sm + 128 * GSTR;           // B tile = W[k], 64 x 64 (stride 68)
    float* SC  = Wm + 64 * WSTR;            // BN scale[64] | shift[64]
    float* RED = SC + 128;                  // stats partials 2 x 4 x 64

    const int tid  = threadIdx.x;
    const int wid  = tid >> 5;
    const int lane = tid & 31;
    const int n0   = blockIdx.x * TILE_M;
    const int r    = tid >> 1;              // tile row this thread gathers
    const int h    = tid & 1;               // channel half
    const int n    = n0 + r;
    const int mr   = wid * 16;              // warp's M offset
    const int gq   = lane >> 2;             // mma group id (0..7)
    const int tq   = lane & 3;              // mma thread-in-group (0..3)

    if (BN_IN) {
        if (tid < 128) SC[tid] = stats_in[tid];
        __syncthreads();    // SC visible to ALL threads before any use (R3 race fix)
    }

    // ---- prefetch offset k = 0 into registers ----
    float4 ga[8];
    float4 wv[4];
    float  m = 0.f;
    {
        int gi = 0;
        if (n < NP) { gi = idx[n]; m = mask[n]; }
        if (m != 0.f) {
            const float4* sp = (const float4*)(src + (size_t)gi * CCH + h * 32);
#pragma unroll
            for (int j = 0; j < 8; ++j) ga[j] = sp[j];
        } else {
#pragma unroll
            for (int j = 0; j < 8; ++j) ga[j] = make_float4(0.f, 0.f, 0.f, 0.f);
        }
        const float4* wp = (const float4*)W;
#pragma unroll
        for (int p = 0; p < 4; ++p) wv[p] = wp[tid + p * 256];
    }

    float acc[8][4];
#pragma unroll
    for (int nb = 0; nb < 8; ++nb)
#pragma unroll
        for (int i = 0; i < 4; ++i) acc[nb][i] = 0.f;

    for (int k = 0; k < KK; ++k) {
        // ---- store prefetched A tile (BN/ReLU + mask + tf32 round) ----
        if (m != 0.f) {
#pragma unroll
            for (int j = 0; j < 8; ++j) {
                float4 x = ga[j];
                if (BN_IN) {
                    const int c4 = h * 32 + j * 4;
                    x.x = fmaxf(fmaf(x.x, SC[c4 + 0], SC[64 + c4 + 0]), 0.f);
                    x.y = fmaxf(fmaf(x.y, SC[c4 + 1], SC[64 + c4 + 1]), 0.f);
                    x.z = fmaxf(fmaf(x.z, SC[c4 + 2], SC[64 + c4 + 2]), 0.f);
                    x.w = fmaxf(fmaf(x.w, SC[c4 + 3], SC[64 + c4 + 3]), 0.f);
                }
                uint4 u;
                u.x = tf32r(x.x); u.y = tf32r(x.y); u.z = tf32r(x.z); u.w = tf32r(x.w);
                *(uint4*)&G[r * GSTR + h * 32 + j * 4] = u;
            }
        } else {
            const uint4 z = make_uint4(0u, 0u, 0u, 0u);
#pragma unroll
            for (int j = 0; j < 8; ++j)
                *(uint4*)&G[r * GSTR + h * 32 + j * 4] = z;
        }
        // ---- store prefetched W tile (tf32 round) ----
#pragma unroll
        for (int p = 0; p < 4; ++p) {
            int i   = tid + p * 256;            // float4 index within 64x64
            int row = i >> 4;
            int col = (i & 15) * 4;
            uint4 u;
            u.x = tf32r(wv[p].x); u.y = tf32r(wv[p].y);
            u.z = tf32r(wv[p].z); u.w = tf32r(wv[p].w);
            *(uint4*)&Wm[row * WSTR + col] = u;
        }
        __syncthreads();   // tile ready for all warps

        // ---- prefetch offset k+1 (hides LDG latency under mma) ----
        if (k + 1 < KK) {
            m = 0.f;
            int gi = 0;
            if (n < NP) { gi = idx[(k + 1) * NP + n]; m = mask[(k + 1) * NP + n]; }
            if (m != 0.f) {
                const float4* sp = (const float4*)(src + (size_t)gi * CCH + h * 32);
#pragma unroll
                for (int j = 0; j < 8; ++j) ga[j] = sp[j];
            } else {
#pragma unroll
                for (int j = 0; j < 8; ++j) ga[j] = make_float4(0.f, 0.f, 0.f, 0.f);
            }
            const float4* wp = (const float4*)(W + (size_t)(k + 1) * CCH * CCH);
#pragma unroll
            for (int p = 0; p < 4; ++p) wv[p] = wp[tid + p * 256];
        }

        // ---- 64 mma.sync per warp: 8 k-steps x 8 n-blocks ----
#pragma unroll
        for (int ks = 0; ks < 8; ++ks) {
            uint32_t a[4];
            const float* Ab = &G[(mr + gq) * GSTR + ks * 8 + tq];
            a[0] = __float_as_uint(Ab[0]);
            a[1] = __float_as_uint(Ab[8 * GSTR]);
            a[2] = __float_as_uint(Ab[4]);
            a[3] = __float_as_uint(Ab[8 * GSTR + 4]);
            const float* Bb0 = &Wm[(ks * 8 + tq) * WSTR + gq];
            const float* Bb1 = &Wm[(ks * 8 + tq + 4) * WSTR + gq];
#pragma unroll
            for (int nb = 0; nb < 8; ++nb) {
                uint32_t b[2];
                b[0] = __float_as_uint(Bb0[nb * 8]);
                b[1] = __float_as_uint(Bb1[nb * 8]);
                mma8(acc[nb], a, b);
            }
        }
        __syncthreads();   // all warps done reading before next STS
    }

    // ---- epilogue: stage C to SMEM (reuse G), write dst, emit stat partials ----
#pragma unroll
    for (int nb = 0; nb < 8; ++nb) {
        *(float2*)&G[(mr + gq)     * GSTR + nb * 8 + 2 * tq] = make_float2(acc[nb][0], acc[nb][1]);
        *(float2*)&G[(mr + gq + 8) * GSTR + nb * 8 + 2 * tq] = make_float2(acc[nb][2], acc[nb][3]);
    }
    __syncthreads();

    if (n < NP) {
#pragma unroll
        for (int j = 0; j < 8; ++j)
            *(float4*)(dst + (size_t)n * CCH + h * 32 + j * 4) =
                *(const float4*)&G[r * GSTR + h * 32 + j * 4];
    }

    // deterministic per-channel partials (rows >= NP hold exact zeros)
    {
        const int c  = tid & 63;
        const int g2 = tid >> 6;
        float s = 0.f, s2 = 0.f;
#pragma unroll
        for (int rr = 0; rr < 32; ++rr) {
            float v = G[(g2 * 32 + rr) * GSTR + c];
            s += v;
            s2 = fmaf(v, v, s2);
        }
        RED[g2 * 64 + c]       = s;
        RED[256 + g2 * 64 + c] = s2;
    }
    __syncthreads();
    if (tid < CCH) {
        float s  = RED[tid]       + RED[64 + tid]       + RED[128 + tid]       + RED[192 + tid];
        float s2 = RED[256 + tid] + RED[320 + tid]      + RED[384 + tid]       + RED[448 + tid];
        part[blockIdx.x * (2 * CCH) + tid]       = s;
        part[blockIdx.x * (2 * CCH) + CCH + tid] = s2;
    }
}

// ---------------------------------------------------------------------------
// Per-channel stats finalize: scale = gamma*rsqrt(var+eps), shift = beta - mean*scale
// ---------------------------------------------------------------------------
__global__ __launch_bounds__(256)
void finalize_kernel(const float* __restrict__ part,
                     const float* __restrict__ gamma,
                     const float* __restrict__ beta,
                     float*       __restrict__ stats)
{
    const int c   = blockIdx.x;
    const int tid = threadIdx.x;
    float s = 0.f, s2 = 0.f;
    for (int b = tid; b < NB2; b += 256) {
        s  += part[b * (2 * CCH) + c];
        s2 += part[b * (2 * CCH) + CCH + c];
    }
    __shared__ float r1[256], r2[256];
    r1[tid] = s; r2[tid] = s2;
    __syncthreads();
    for (int o = 128; o > 0; o >>= 1) {
        if (tid < o) { r1[tid] += r1[tid + o]; r2[tid] += r2[tid + o]; }
        __syncthreads();
    }
    if (tid == 0) {
        float mean = r1[0] * (1.0f / NP);
        float var  = r2[0] * (1.0f / NP) - mean * mean;
        float istd = rsqrtf(var + EPSV);
        float sc   = istd * gamma[c];
        stats[c]       = sc;
        stats[CCH + c] = beta[c] - mean * sc;
    }
}

// ---------------------------------------------------------------------------
// out = relu( buf2*scale2 + shift2 + feats )
// ---------------------------------------------------------------------------
__global__ __launch_bounds__(256)
void epi_kernel(const float* __restrict__ buf2,
                const float* __restrict__ stats,
                const float* __restrict__ feats,
                float*       __restrict__ out)
{
    __shared__ float sc[CCH], sh[CCH];
    if (threadIdx.x < CCH) {
        sc[threadIdx.x] = stats[threadIdx.x];
        sh[threadIdx.x] = stats[CCH + threadIdx.x];
    }
    __syncthreads();
    int i = blockIdx.x * blockDim.x + threadIdx.x;   // float4 index
    if (i < NP * CCH / 4) {
        float4 v = ((const float4*)buf2)[i];
        float4 f = ((const float4*)feats)[i];
        int c = (i * 4) & 63;
        v.x = fmaxf(fmaf(v.x, sc[c + 0], sh[c + 0]) + f.x, 0.f);
        v.y = fmaxf(fmaf(v.y, sc[c + 1], sh[c + 1]) + f.y, 0.f);
        v.z = fmaxf(fmaf(v.z, sc[c + 2], sh[c + 2]) + f.z, 0.f);
        v.w = fmaxf(fmaf(v.w, sc[c + 3], sh[c + 3]) + f.w, 0.f);
        ((float4*)out)[i] = v;
    }
}

// ---------------------------------------------------------------------------
extern "C" void kernel_launch(void* const* d_in, const int* in_sizes, int n_in,
                              void* d_out, int out_size)
{
    const float* feats  = (const float*)d_in[0];
    const float* W1     = (const float*)d_in[1];
    const float* gamma1 = (const float*)d_in[2];
    const float* beta1  = (const float*)d_in[3];
    const float* W2     = (const float*)d_in[4];
    const float* gamma2 = (const float*)d_in[5];
    const float* beta2  = (const float*)d_in[6];
    const int*   idx1   = (const int*)  d_in[7];
    const float* mask1  = (const float*)d_in[8];
    const int*   idx2   = (const int*)  d_in[9];
    const float* mask2  = (const float*)d_in[10];
    float* out = (float*)d_out;

    float *buf1, *buf2, *part1, *part2, *st1, *st2;
    cudaGetSymbolAddress((void**)&buf1,  g_buf1);
    cudaGetSymbolAddress((void**)&buf2,  g_buf2);
    cudaGetSymbolAddress((void**)&part1, g_part1);
    cudaGetSymbolAddress((void**)&part2, g_part2);
    cudaGetSymbolAddress((void**)&st1,   g_stats1);
    cudaGetSymbolAddress((void**)&st2,   g_stats2);

    cudaFuncSetAttribute(conv_mma<false>, cudaFuncAttributeMaxDynamicSharedMemorySize, SMEM_BYTES);
    cudaFuncSetAttribute(conv_mma<true>,  cudaFuncAttributeMaxDynamicSharedMemorySize, SMEM_BYTES);

    conv_mma<false><<<NB2, 256, SMEM_BYTES>>>(feats, idx1, mask1, W1, nullptr, buf1, part1);
    finalize_kernel<<<CCH, 256>>>(part1, gamma1, beta1, st1);
    conv_mma<true><<<NB2, 256, SMEM_BYTES>>>(buf1, idx2, mask2, W2, st1, buf2, part2);
    finalize_kernel<<<CCH, 256>>>(part2, gamma2, beta2, st2);

    int epi_blocks = (NP * CCH / 4 + 255) / 256;
    epi_kernel<<<epi_blocks, 256>>>(buf2, st2, feats, out);
}

// round 5
// speedup vs baseline: 3.8044x; 3.1043x over previous
#include <cuda_runtime.h>
#include <cuda_fp16.h>
#include <cstdint>

#define NP     100000
#define CCH    64
#define KK     27
#define EPSV   1e-5f
#define TILE_M 128
#define NB2    ((NP + TILE_M - 1) / TILE_M)   // 782

// ---------------- scratch (device globals; no allocation allowed) ----------------
__device__ float g_buf1[NP * CCH];
__device__ float g_buf2[NP * CCH];
__device__ __align__(16) __half g_h0[NP * CCH];          // half(feats)
__device__ __align__(16) __half g_h1[NP * CCH];          // half(relu(bn1(buf1)))
__device__ __align__(16) __half g_wh1[KK * CCH * CCH];   // Wh[k][d][c] = half(W[k][c][d])
__device__ __align__(16) __half g_wh2[KK * CCH * CCH];
__device__ float g_part1[NB2 * 2 * CCH];
__device__ float g_part2[NB2 * 2 * CCH];
__device__ float g_stats1[2 * CCH];   // [0:64) scale, [64:128) shift
__device__ float g_stats2[2 * CCH];

// ---------------- PTX helpers ----------------
__device__ __forceinline__ void ldsm4(uint32_t& r0, uint32_t& r1, uint32_t& r2, uint32_t& r3,
                                      uint32_t addr) {
    asm volatile("ldmatrix.sync.aligned.m8n8.x4.shared.b16 {%0,%1,%2,%3}, [%4];"
                 : "=r"(r0), "=r"(r1), "=r"(r2), "=r"(r3) : "r"(addr));
}
__device__ __forceinline__ void mma16816(float* d, uint32_t a0, uint32_t a1, uint32_t a2,
                                         uint32_t a3, uint32_t b0, uint32_t b1) {
    asm volatile(
        "mma.sync.aligned.m16n8k16.row.col.f32.f16.f16.f32 "
        "{%0,%1,%2,%3}, {%4,%5,%6,%7}, {%8,%9}, {%0,%1,%2,%3};"
        : "+f"(d[0]), "+f"(d[1]), "+f"(d[2]), "+f"(d[3])
        : "r"(a0), "r"(a1), "r"(a2), "r"(a3), "r"(b0), "r"(b1));
}
#define STS128A(addr, v) \
    asm volatile("st.shared.v4.b32 [%0], {%1,%2,%3,%4};" \
                 :: "r"(addr), "r"((v).x), "r"((v).y), "r"((v).z), "r"((v).w))

// SMEM map (byte offsets from 128-aligned base):
//   GEMM phase:    A tile [128 rows x 128B, SW128]   @ 0      (16384 B)
//                  B tile [ 64 rows x 128B, SW128]   @ 16384  ( 8192 B)
//   Epilogue:      C staging 128 x 68 fp32           @ 0      (34816 B)
//                  RED partials 512 fp32             @ 34816  ( 2048 B)
#define SM_B_OFF   16384u
#define SM_RED_OFF 34816
#define SMEM_BYTES (36864 + 128)

// ---------------------------------------------------------------------------
// Sparse conv: dst[n,d] = sum_k sum_c src_h[idx[k,n]][c] * mask[k,n] * Wh[k][d][c]
// fp16 operands (pre-converted), fp32 accum, fused deterministic BN-stat partials.
// ---------------------------------------------------------------------------
__global__ __launch_bounds__(256, 2)
void conv_h(const __half* __restrict__ src,
            const int*    __restrict__ idx,
            const float*  __restrict__ mask,
            const __half* __restrict__ Wh,
            float*        __restrict__ dst,
            float*        __restrict__ part)
{
    extern __shared__ char smraw[];
    char* smc = (char*)(((uintptr_t)smraw + 127) & ~(uintptr_t)127);
    uint32_t sb;
    asm("{ .reg .u64 t; cvta.to.shared.u64 t, %1; cvt.u32.u64 %0, t; }" : "=r"(sb) : "l"(smc));
    float* ST  = (float*)smc;
    float* RED = (float*)(smc + SM_RED_OFF);

    const int tid  = threadIdx.x;
    const int wid  = tid >> 5;
    const int lane = tid & 31;
    const int n0   = blockIdx.x * TILE_M;
    const int r    = tid >> 1;           // gather row
    const int h    = tid & 1;            // row half (32 ch = 64 B)
    const int n    = n0 + r;
    const int mr   = wid * 16;           // warp M offset
    const int gq   = lane >> 2;
    const int tq   = lane & 3;
    const int mrow = lane & 7;
    const int mi   = lane >> 3;

    // ---- loop-invariant LDSM addresses (SW128 swizzled) ----
    uint32_t a_addr[4], b_base[4];
#pragma unroll
    for (int ks = 0; ks < 4; ++ks) {
        a_addr[ks] = sb + (uint32_t)(mr + (mi & 1) * 8 + mrow) * 128u
                        + (uint32_t)((2 * ks + (mi >> 1)) ^ mrow) * 16u;
        b_base[ks] = sb + SM_B_OFF + (uint32_t)((mi >> 1) * 8 + mrow) * 128u
                        + (uint32_t)((2 * ks + (mi & 1)) ^ mrow) * 16u;
    }
    // gather-store addresses (4 x 16B chunks per thread, SW128)
    uint32_t g_st[4];
#pragma unroll
    for (int j = 0; j < 4; ++j)
        g_st[j] = sb + (uint32_t)r * 128u + (uint32_t)((h * 4 + j) ^ (r & 7)) * 16u;
    // W-store addresses (2 x 16B chunks per thread, SW128)
    uint32_t w_st[2];
#pragma unroll
    for (int i = 0; i < 2; ++i) {
        int lin = 2 * tid + i;
        int d = lin >> 3, cc = lin & 7;
        w_st[i] = sb + SM_B_OFF + (uint32_t)d * 128u + (uint32_t)(cc ^ (d & 7)) * 16u;
    }

    // ---- prefetch offset k = 0 ----
    uint4 ga[4], wv[2];
    float m = 0.f;
    {
        int gi = 0;
        if (n < NP) { gi = idx[n]; m = mask[n]; }
        const uint4* sp = (const uint4*)src + (size_t)gi * 8 + h * 4;
        if (m != 0.f) { ga[0] = sp[0]; ga[1] = sp[1]; ga[2] = sp[2]; ga[3] = sp[3]; }
        else { ga[0] = ga[1] = ga[2] = ga[3] = make_uint4(0u, 0u, 0u, 0u); }
        const uint4* wp = (const uint4*)Wh;
        wv[0] = wp[2 * tid]; wv[1] = wp[2 * tid + 1];
    }

    float acc[8][4];
#pragma unroll
    for (int nb = 0; nb < 8; ++nb)
#pragma unroll
        for (int i = 0; i < 4; ++i) acc[nb][i] = 0.f;

    for (int k = 0; k < KK; ++k) {
        // ---- store prefetched tiles ----
        STS128A(g_st[0], ga[0]); STS128A(g_st[1], ga[1]);
        STS128A(g_st[2], ga[2]); STS128A(g_st[3], ga[3]);
        STS128A(w_st[0], wv[0]); STS128A(w_st[1], wv[1]);
        __syncthreads();   // tiles ready

        // ---- prefetch offset k+1 (hides LDG under MMA) ----
        if (k + 1 < KK) {
            m = 0.f;
            int gi = 0;
            if (n < NP) { gi = idx[(k + 1) * NP + n]; m = mask[(k + 1) * NP + n]; }
            const uint4* sp = (const uint4*)src + (size_t)gi * 8 + h * 4;
            if (m != 0.f) { ga[0] = sp[0]; ga[1] = sp[1]; ga[2] = sp[2]; ga[3] = sp[3]; }
            else { ga[0] = ga[1] = ga[2] = ga[3] = make_uint4(0u, 0u, 0u, 0u); }
            const uint4* wp = (const uint4*)(Wh + (size_t)(k + 1) * CCH * CCH);
            wv[0] = wp[2 * tid]; wv[1] = wp[2 * tid + 1];
        }

        // ---- MMA: 4 k-steps (k16) x 8 n-blocks, operands via ldmatrix ----
#pragma unroll
        for (int ks = 0; ks < 4; ++ks) {
            uint32_t a0, a1, a2, a3;
            ldsm4(a0, a1, a2, a3, a_addr[ks]);
#pragma unroll
            for (int nbp = 0; nbp < 4; ++nbp) {
                uint32_t b0, b1, b2, b3;
                ldsm4(b0, b1, b2, b3, b_base[ks] + (uint32_t)nbp * 2048u);
                mma16816(acc[2 * nbp],     a0, a1, a2, a3, b0, b1);
                mma16816(acc[2 * nbp + 1], a0, a1, a2, a3, b2, b3);
            }
        }
        __syncthreads();   // all warps done reading before next STS
    }

    // ---- epilogue: stage C (fp32), write dst, deterministic stat partials ----
#pragma unroll
    for (int nb = 0; nb < 8; ++nb) {
        *(float2*)&ST[(mr + gq)     * 68 + nb * 8 + 2 * tq] = make_float2(acc[nb][0], acc[nb][1]);
        *(float2*)&ST[(mr + gq + 8) * 68 + nb * 8 + 2 * tq] = make_float2(acc[nb][2], acc[nb][3]);
    }
    __syncthreads();

    if (n < NP) {
#pragma unroll
        for (int j = 0; j < 8; ++j)
            *(float4*)(dst + (size_t)n * CCH + h * 32 + j * 4) =
                *(const float4*)&ST[r * 68 + h * 32 + j * 4];
    }
    {
        const int c  = tid & 63;
        const int g2 = tid >> 6;
        float s = 0.f, s2 = 0.f;
#pragma unroll
        for (int rr = 0; rr < 32; ++rr) {
            float v = ST[(g2 * 32 + rr) * 68 + c];  // rows >= NP are exact zeros
            s += v;
            s2 = fmaf(v, v, s2);
        }
        RED[g2 * 64 + c]       = s;
        RED[256 + g2 * 64 + c] = s2;
    }
    __syncthreads();
    if (tid < CCH) {
        float s  = RED[tid]       + RED[64 + tid]  + RED[128 + tid] + RED[192 + tid];
        float s2 = RED[256 + tid] + RED[320 + tid] + RED[384 + tid] + RED[448 + tid];
        part[blockIdx.x * (2 * CCH) + tid]       = s;
        part[blockIdx.x * (2 * CCH) + CCH + tid] = s2;
    }
}

// ---------------------------------------------------------------------------
// prep: Wh[k][d][c] = half(W[k][c][d])   (transpose + convert, once per replay)
// ---------------------------------------------------------------------------
__global__ __launch_bounds__(256)
void prep_w(const float* __restrict__ W, __half* __restrict__ Wh)
{
    int k = blockIdx.x;
    const float* Wk = W  + (size_t)k * CCH * CCH;
    __half*      Wo = Wh + (size_t)k * CCH * CCH;
    for (int i = threadIdx.x; i < CCH * CCH; i += 256) {
        int d = i >> 6, c = i & 63;
        Wo[i] = __float2half_rn(Wk[c * CCH + d]);
    }
}

// ---------------------------------------------------------------------------
// feats -> half  (8 elements / thread)
// ---------------------------------------------------------------------------
__global__ __launch_bounds__(256)
void f2h_kernel(const float* __restrict__ in, __half* __restrict__ out)
{
    int i = blockIdx.x * 256 + threadIdx.x;
    if (i < NP * CCH / 8) {
        const float4* p = (const float4*)in + 2 * i;
        float4 v0 = p[0], v1 = p[1];
        union { __half2 hh[4]; uint4 u; } cv;
        cv.hh[0] = __floats2half2_rn(v0.x, v0.y);
        cv.hh[1] = __floats2half2_rn(v0.z, v0.w);
        cv.hh[2] = __floats2half2_rn(v1.x, v1.y);
        cv.hh[3] = __floats2half2_rn(v1.z, v1.w);
        ((uint4*)out)[i] = cv.u;
    }
}

// ---------------------------------------------------------------------------
// h1 = half(relu(buf1*scale1 + shift1))   (8 elements / thread)
// ---------------------------------------------------------------------------
__global__ __launch_bounds__(256)
void bnrelu2h_kernel(const float* __restrict__ in, const float* __restrict__ stats,
                     __half* __restrict__ out)
{
    __shared__ float scsh[128];
    if (threadIdx.x < 128) scsh[threadIdx.x] = stats[threadIdx.x];
    __syncthreads();
    int i = blockIdx.x * 256 + threadIdx.x;
    if (i < NP * CCH / 8) {
        const float4* p = (const float4*)in + 2 * i;
        float4 v0 = p[0], v1 = p[1];
        int c0 = (i * 8) & 63;
        const float* sc = scsh, * sh = scsh + 64;
        float t[8];
        t[0] = fmaxf(fmaf(v0.x, sc[c0 + 0], sh[c0 + 0]), 0.f);
        t[1] = fmaxf(fmaf(v0.y, sc[c0 + 1], sh[c0 + 1]), 0.f);
        t[2] = fmaxf(fmaf(v0.z, sc[c0 + 2], sh[c0 + 2]), 0.f);
        t[3] = fmaxf(fmaf(v0.w, sc[c0 + 3], sh[c0 + 3]), 0.f);
        t[4] = fmaxf(fmaf(v1.x, sc[c0 + 4], sh[c0 + 4]), 0.f);
        t[5] = fmaxf(fmaf(v1.y, sc[c0 + 5], sh[c0 + 5]), 0.f);
        t[6] = fmaxf(fmaf(v1.z, sc[c0 + 6], sh[c0 + 6]), 0.f);
        t[7] = fmaxf(fmaf(v1.w, sc[c0 + 7], sh[c0 + 7]), 0.f);
        union { __half2 hh[4]; uint4 u; } cv;
        cv.hh[0] = __floats2half2_rn(t[0], t[1]);
        cv.hh[1] = __floats2half2_rn(t[2], t[3]);
        cv.hh[2] = __floats2half2_rn(t[4], t[5]);
        cv.hh[3] = __floats2half2_rn(t[6], t[7]);
        ((uint4*)out)[i] = cv.u;
    }
}

// ---------------------------------------------------------------------------
// Per-channel stats finalize: scale = gamma*rsqrt(var+eps), shift = beta - mean*scale
// ---------------------------------------------------------------------------
__global__ __launch_bounds__(256)
void finalize_kernel(const float* __restrict__ part,
                     const float* __restrict__ gamma,
                     const float* __restrict__ beta,
                     float*       __restrict__ stats)
{
    const int c   = blockIdx.x;
    const int tid = threadIdx.x;
    float s = 0.f, s2 = 0.f;
    for (int b = tid; b < NB2; b += 256) {
        s  += part[b * (2 * CCH) + c];
        s2 += part[b * (2 * CCH) + CCH + c];
    }
    __shared__ float r1[256], r2[256];
    r1[tid] = s; r2[tid] = s2;
    __syncthreads();
    for (int o = 128; o > 0; o >>= 1) {
        if (tid < o) { r1[tid] += r1[tid + o]; r2[tid] += r2[tid + o]; }
        __syncthreads();
    }
    if (tid == 0) {
        float mean = r1[0] * (1.0f / NP);
        float var  = r2[0] * (1.0f / NP) - mean * mean;
        float istd = rsqrtf(var + EPSV);
        float sc   = istd * gamma[c];
        stats[c]       = sc;
        stats[CCH + c] = beta[c] - mean * sc;
    }
}

// ---------------------------------------------------------------------------
// out = relu( buf2*scale2 + shift2 + feats )
// ---------------------------------------------------------------------------
__global__ __launch_bounds__(256)
void epi_kernel(const float* __restrict__ buf2,
                const float* __restrict__ stats,
                const float* __restrict__ feats,
                float*       __restrict__ out)
{
    __shared__ float sc[CCH], sh[CCH];
    if (threadIdx.x < CCH) {
        sc[threadIdx.x] = stats[threadIdx.x];
        sh[threadIdx.x] = stats[CCH + threadIdx.x];
    }
    __syncthreads();
    int i = blockIdx.x * blockDim.x + threadIdx.x;   // float4 index
    if (i < NP * CCH / 4) {
        float4 v = ((const float4*)buf2)[i];
        float4 f = ((const float4*)feats)[i];
        int c = (i * 4) & 63;
        v.x = fmaxf(fmaf(v.x, sc[c + 0], sh[c + 0]) + f.x, 0.f);
        v.y = fmaxf(fmaf(v.y, sc[c + 1], sh[c + 1]) + f.y, 0.f);
        v.z = fmaxf(fmaf(v.z, sc[c + 2], sh[c + 2]) + f.z, 0.f);
        v.w = fmaxf(fmaf(v.w, sc[c + 3], sh[c + 3]) + f.w, 0.f);
        ((float4*)out)[i] = v;
    }
}

// ---------------------------------------------------------------------------
extern "C" void kernel_launch(void* const* d_in, const int* in_sizes, int n_in,
                              void* d_out, int out_size)
{
    const float* feats  = (const float*)d_in[0];
    const float* W1     = (const float*)d_in[1];
    const float* gamma1 = (const float*)d_in[2];
    const float* beta1  = (const float*)d_in[3];
    const float* W2     = (const float*)d_in[4];
    const float* gamma2 = (const float*)d_in[5];
    const float* beta2  = (const float*)d_in[6];
    const int*   idx1   = (const int*)  d_in[7];
    const float* mask1  = (const float*)d_in[8];
    const int*   idx2   = (const int*)  d_in[9];
    const float* mask2  = (const float*)d_in[10];
    float* out = (float*)d_out;

    float *buf1, *buf2, *part1, *part2, *st1, *st2;
    __half *h0, *h1, *wh1, *wh2;
    cudaGetSymbolAddress((void**)&buf1,  g_buf1);
    cudaGetSymbolAddress((void**)&buf2,  g_buf2);
    cudaGetSymbolAddress((void**)&h0,    g_h0);
    cudaGetSymbolAddress((void**)&h1,    g_h1);
    cudaGetSymbolAddress((void**)&wh1,   g_wh1);
    cudaGetSymbolAddress((void**)&wh2,   g_wh2);
    cudaGetSymbolAddress((void**)&part1, g_part1);
    cudaGetSymbolAddress((void**)&part2, g_part2);
    cudaGetSymbolAddress((void**)&st1,   g_stats1);
    cudaGetSymbolAddress((void**)&st2,   g_stats2);

    cudaFuncSetAttribute(conv_h, cudaFuncAttributeMaxDynamicSharedMemorySize, SMEM_BYTES);

    const int cvt_blocks = (NP * CCH / 8 + 255) / 256;
    prep_w<<<KK, 256>>>(W1, wh1);
    prep_w<<<KK, 256>>>(W2, wh2);
    f2h_kernel<<<cvt_blocks, 256>>>(feats, h0);

    conv_h<<<NB2, 256, SMEM_BYTES>>>(h0, idx1, mask1, wh1, buf1, part1);
    finalize_kernel<<<CCH, 256>>>(part1, gamma1, beta1, st1);
    bnrelu2h_kernel<<<cvt_blocks, 256>>>(buf1, st1, h1);
    conv_h<<<NB2, 256, SMEM_BYTES>>>(h1, idx2, mask2, wh2, buf2, part2);
    finalize_kernel<<<CCH, 256>>>(part2, gamma2, beta2, st2);

    const int epi_blocks = (NP * CCH / 4 + 255) / 256;
    epi_kernel<<<epi_blocks, 256>>>(buf2, st2, feats, out);
}

// round 6
// speedup vs baseline: 4.0633x; 1.0680x over previous
#include <cuda_runtime.h>
#include <cuda_fp16.h>
#include <cstdint>

#define NP     100000
#define CCH    64
#define KK     27
#define EPSV   1e-5f
#define TILE_M 256
#define NBC    ((NP + TILE_M - 1) / TILE_M)   // 391

// ---------------- scratch (device globals; no allocation allowed) ----------------
__device__ float g_buf1[NP * CCH];
__device__ float g_buf2[NP * CCH];
__device__ __align__(16) __half g_h0[NP * CCH];          // half(feats)
__device__ __align__(16) __half g_h1[NP * CCH];          // half(relu(bn1(buf1)))
__device__ __align__(16) __half g_wh1[KK * CCH * CCH];   // Wh[k][d][c] = half(W[k][c][d])
__device__ __align__(16) __half g_wh2[KK * CCH * CCH];
__device__ float g_part1[NBC * 2 * CCH];
__device__ float g_part2[NBC * 2 * CCH];
__device__ float g_stats1[2 * CCH];   // [0:64) scale, [64:128) shift
__device__ float g_stats2[2 * CCH];

// ---------------- PTX helpers ----------------
__device__ __forceinline__ void ldsm4(uint32_t& r0, uint32_t& r1, uint32_t& r2, uint32_t& r3,
                                      uint32_t addr) {
    asm volatile("ldmatrix.sync.aligned.m8n8.x4.shared.b16 {%0,%1,%2,%3}, [%4];"
                 : "=r"(r0), "=r"(r1), "=r"(r2), "=r"(r3) : "r"(addr));
}
__device__ __forceinline__ void mma16816(float* d, uint32_t a0, uint32_t a1, uint32_t a2,
                                         uint32_t a3, uint32_t b0, uint32_t b1) {
    asm volatile(
        "mma.sync.aligned.m16n8k16.row.col.f32.f16.f16.f32 "
        "{%0,%1,%2,%3}, {%4,%5,%6,%7}, {%8,%9}, {%0,%1,%2,%3};"
        : "+f"(d[0]), "+f"(d[1]), "+f"(d[2]), "+f"(d[3])
        : "r"(a0), "r"(a1), "r"(a2), "r"(a3), "r"(b0), "r"(b1));
}
#define CP_ASYNC_Z(dst, src, sz) \
    asm volatile("cp.async.cg.shared.global [%0], [%1], 16, %2;" \
                 :: "r"(dst), "l"(src), "r"(sz) : "memory")
#define CP_ASYNC(dst, src) \
    asm volatile("cp.async.cg.shared.global [%0], [%1], 16;" :: "r"(dst), "l"(src) : "memory")
#define CP_COMMIT()  asm volatile("cp.async.commit_group;" ::: "memory")
#define CP_WAIT0()   asm volatile("cp.async.wait_group 0;" ::: "memory")

// SMEM map (byte offsets from 1024-aligned base):
//   A buffers: 256 rows x 128B, SW128   @ 0, 32768
//   B buffers:  64 rows x 128B, SW128   @ 65536, 73728
//   RED/RED2:  512 + 512 fp32           @ 81920, 83968
#define SM_AB(s)   ((uint32_t)(((s) & 1) * 32768))
#define SM_BB(s)   ((uint32_t)(65536 + ((s) & 1) * 8192))
#define SM_RED     81920
#define SM_RED2    83968
#define SMEM_BYTES (86016 + 1024)

// ---------------------------------------------------------------------------
// Sparse conv: dst[n,d] = sum_k sum_c src_h[idx[k,n]][c] * mask[k,n] * Wh[k][d][c]
// fp16 operands, fp32 accum; cp.async double-buffered gather; TILE_M=256;
// fused deterministic BN-stat partials via shuffle reduction.
// ---------------------------------------------------------------------------
__global__ __launch_bounds__(256, 2)
void conv_h(const __half* __restrict__ src,
            const int*    __restrict__ idx,
            const float*  __restrict__ mask,
            const __half* __restrict__ Wh,
            float*        __restrict__ dst,
            float*        __restrict__ part)
{
    extern __shared__ char smraw[];
    char* smc = (char*)(((uintptr_t)smraw + 1023) & ~(uintptr_t)1023);
    uint32_t sb;
    asm("{ .reg .u64 t; cvta.to.shared.u64 t, %1; cvt.u32.u64 %0, t; }" : "=r"(sb) : "l"(smc));
    float* RED  = (float*)(smc + SM_RED);
    float* RED2 = (float*)(smc + SM_RED2);

    const int tid  = threadIdx.x;
    const int w    = tid >> 5;
    const int lane = tid & 31;
    const int n0   = blockIdx.x * TILE_M;
    const int row  = tid;                 // gather row (one full row per thread)
    const int n    = n0 + row;
    const int rs   = row & 7;
    const int gq   = lane >> 2;
    const int tq   = lane & 3;
    const int mrow = lane & 7;
    const int mi   = lane >> 3;

    // loop-invariant LDSM addresses (relative; add buffer base at use)
    uint32_t a_rel[4], b_rel[4];
#pragma unroll
    for (int ks = 0; ks < 4; ++ks) {
        a_rel[ks] = (uint32_t)(w * 32 + (mi & 1) * 8 + mrow) * 128u
                  + (uint32_t)((2 * ks + (mi >> 1)) ^ mrow) * 16u;
        b_rel[ks] = (uint32_t)((mi >> 1) * 8 + mrow) * 128u
                  + (uint32_t)((2 * ks + (mi & 1)) ^ mrow) * 16u;
    }
    // W chunk assignment: chunks 2*tid, 2*tid+1 (16B each)
    const int c16_0 = 2 * tid, c16_1 = 2 * tid + 1;
    const uint32_t wd0 = (uint32_t)(c16_0 >> 3) * 128u + (uint32_t)((c16_0 & 7) ^ ((c16_0 >> 3) & 7)) * 16u;
    const uint32_t wd1 = (uint32_t)(c16_1 >> 3) * 128u + (uint32_t)((c16_1 & 7) ^ ((c16_1 >> 3) & 7)) * 16u;

    // ---- prologue: issue stage 0, prefetch idx/mask for stage 1 ----
    int   idx_c = 0;
    float m_c   = 0.f;
    if (n < NP) { idx_c = idx[n]; m_c = mask[n]; }
    {
        const char* gp = (const char*)(src + (size_t)idx_c * CCH);
        uint32_t abase = sb + SM_AB(0) + (uint32_t)row * 128u;
        uint32_t sz = (m_c != 0.f) ? 16u : 0u;
#pragma unroll
        for (int j = 0; j < 8; ++j)
            CP_ASYNC_Z(abase + (uint32_t)((j ^ rs) * 16), gp + j * 16, sz);
        const char* wp = (const char*)Wh;
        uint32_t bbase = sb + SM_BB(0);
        CP_ASYNC(bbase + wd0, wp + c16_0 * 16);
        CP_ASYNC(bbase + wd1, wp + c16_1 * 16);
        CP_COMMIT();
    }
    idx_c = 0; m_c = 0.f;
    if (n < NP) { idx_c = idx[NP + n]; m_c = mask[NP + n]; }

    float acc[2][8][4];
#pragma unroll
    for (int t = 0; t < 2; ++t)
#pragma unroll
        for (int nb = 0; nb < 8; ++nb)
#pragma unroll
            for (int i = 0; i < 4; ++i) acc[t][nb][i] = 0.f;

    for (int k = 0; k < KK; ++k) {
        CP_WAIT0();            // stage k resident (own groups)
        __syncthreads();       // everyone's stage k resident; mma(k-1) fully done

        // ---- issue stage k+1 (overlaps with mma k) ----
        if (k + 1 < KK) {
            const char* gp = (const char*)(src + (size_t)idx_c * CCH);
            uint32_t abase = sb + SM_AB(k + 1) + (uint32_t)row * 128u;
            uint32_t sz = (m_c != 0.f) ? 16u : 0u;
#pragma unroll
            for (int j = 0; j < 8; ++j)
                CP_ASYNC_Z(abase + (uint32_t)((j ^ rs) * 16), gp + j * 16, sz);
            const char* wp = (const char*)(Wh + (size_t)(k + 1) * CCH * CCH);
            uint32_t bbase = sb + SM_BB(k + 1);
            CP_ASYNC(bbase + wd0, wp + c16_0 * 16);
            CP_ASYNC(bbase + wd1, wp + c16_1 * 16);
            CP_COMMIT();
            // prefetch idx/mask for stage k+2
            idx_c = 0; m_c = 0.f;
            if (k + 2 < KK && n < NP) {
                idx_c = idx[(size_t)(k + 2) * NP + n];
                m_c   = mask[(size_t)(k + 2) * NP + n];
            }
        }

        // ---- MMA on buffer k: 4 k-steps x (2 m-tiles x 8 n-blocks) ----
        const uint32_t ab = sb + SM_AB(k);
        const uint32_t bb = sb + SM_BB(k);
#pragma unroll
        for (int ks = 0; ks < 4; ++ks) {
            uint32_t a00, a01, a02, a03, a10, a11, a12, a13;
            ldsm4(a00, a01, a02, a03, ab + a_rel[ks]);
            ldsm4(a10, a11, a12, a13, ab + a_rel[ks] + 2048u);   // mtile 1 (+16 rows)
#pragma unroll
            for (int nbp = 0; nbp < 4; ++nbp) {
                uint32_t b0, b1, b2, b3;
                ldsm4(b0, b1, b2, b3, bb + b_rel[ks] + (uint32_t)nbp * 2048u);
                mma16816(acc[0][2 * nbp],     a00, a01, a02, a03, b0, b1);
                mma16816(acc[0][2 * nbp + 1], a00, a01, a02, a03, b2, b3);
                mma16816(acc[1][2 * nbp],     a10, a11, a12, a13, b0, b1);
                mma16816(acc[1][2 * nbp + 1], a10, a11, a12, a13, b2, b3);
            }
        }
        // no trailing bar: next iteration's CP_WAIT0+bar orders reuse
    }

    // ---- epilogue: direct dst stores + shuffle-reduced BN partials ----
#pragma unroll
    for (int t = 0; t < 2; ++t) {
#pragma unroll
        for (int nb = 0; nb < 8; ++nb) {
            int rlo = n0 + w * 32 + t * 16 + gq;
            if (rlo < NP)
                *(float2*)(dst + (size_t)rlo * CCH + nb * 8 + 2 * tq) =
                    make_float2(acc[t][nb][0], acc[t][nb][1]);
            if (rlo + 8 < NP)
                *(float2*)(dst + (size_t)(rlo + 8) * CCH + nb * 8 + 2 * tq) =
                    make_float2(acc[t][nb][2], acc[t][nb][3]);
        }
    }
    // per-column (channel) sums over this warp's 32 rows; rows >= NP are exact zeros
#pragma unroll
    for (int cidx = 0; cidx < 16; ++cidx) {
        const int nb = cidx >> 1, j = cidx & 1;
        float p = acc[0][nb][j] + acc[0][nb][2 + j] + acc[1][nb][j] + acc[1][nb][2 + j];
        float q = acc[0][nb][j] * acc[0][nb][j];
        q = fmaf(acc[0][nb][2 + j], acc[0][nb][2 + j], q);
        q = fmaf(acc[1][nb][j],     acc[1][nb][j],     q);
        q = fmaf(acc[1][nb][2 + j], acc[1][nb][2 + j], q);
#pragma unroll
        for (int d = 4; d < 32; d <<= 1) {      // reduce over gq (lanes stride 4)
            p += __shfl_xor_sync(0xFFFFFFFFu, p, d);
            q += __shfl_xor_sync(0xFFFFFFFFu, q, d);
        }
        if (lane < 4) {                          // gq == 0
            RED[w * 64 + nb * 8 + 2 * tq + j]  = p;
            RED2[w * 64 + nb * 8 + 2 * tq + j] = q;
        }
    }
    __syncthreads();
    if (tid < CCH) {
        float s = 0.f, s2 = 0.f;
#pragma unroll
        for (int ww = 0; ww < 8; ++ww) { s += RED[ww * 64 + tid]; s2 += RED2[ww * 64 + tid]; }
        part[blockIdx.x * (2 * CCH) + tid]       = s;
        part[blockIdx.x * (2 * CCH) + CCH + tid] = s2;
    }
}

// ---------------------------------------------------------------------------
// prep: Wh[k][d][c] = half(W[k][c][d])
// ---------------------------------------------------------------------------
__global__ __launch_bounds__(256)
void prep_w(const float* __restrict__ W, __half* __restrict__ Wh)
{
    int k = blockIdx.x;
    const float* Wk = W  + (size_t)k * CCH * CCH;
    __half*      Wo = Wh + (size_t)k * CCH * CCH;
    for (int i = threadIdx.x; i < CCH * CCH; i += 256) {
        int d = i >> 6, c = i & 63;
        Wo[i] = __float2half_rn(Wk[c * CCH + d]);
    }
}

// ---------------------------------------------------------------------------
// feats -> half  (8 elements / thread)
// ---------------------------------------------------------------------------
__global__ __launch_bounds__(256)
void f2h_kernel(const float* __restrict__ in, __half* __restrict__ out)
{
    int i = blockIdx.x * 256 + threadIdx.x;
    if (i < NP * CCH / 8) {
        const float4* p = (const float4*)in + 2 * i;
        float4 v0 = p[0], v1 = p[1];
        union { __half2 hh[4]; uint4 u; } cv;
        cv.hh[0] = __floats2half2_rn(v0.x, v0.y);
        cv.hh[1] = __floats2half2_rn(v0.z, v0.w);
        cv.hh[2] = __floats2half2_rn(v1.x, v1.y);
        cv.hh[3] = __floats2half2_rn(v1.z, v1.w);
        ((uint4*)out)[i] = cv.u;
    }
}

// ---------------------------------------------------------------------------
// h1 = half(relu(buf1*scale1 + shift1))   (8 elements / thread)
// ---------------------------------------------------------------------------
__global__ __launch_bounds__(256)
void bnrelu2h_kernel(const float* __restrict__ in, const float* __restrict__ stats,
                     __half* __restrict__ out)
{
    __shared__ float scsh[128];
    if (threadIdx.x < 128) scsh[threadIdx.x] = stats[threadIdx.x];
    __syncthreads();
    int i = blockIdx.x * 256 + threadIdx.x;
    if (i < NP * CCH / 8) {
        const float4* p = (const float4*)in + 2 * i;
        float4 v0 = p[0], v1 = p[1];
        int c0 = (i * 8) & 63;
        const float* sc = scsh, * sh = scsh + 64;
        float t[8];
        t[0] = fmaxf(fmaf(v0.x, sc[c0 + 0], sh[c0 + 0]), 0.f);
        t[1] = fmaxf(fmaf(v0.y, sc[c0 + 1], sh[c0 + 1]), 0.f);
        t[2] = fmaxf(fmaf(v0.z, sc[c0 + 2], sh[c0 + 2]), 0.f);
        t[3] = fmaxf(fmaf(v0.w, sc[c0 + 3], sh[c0 + 3]), 0.f);
        t[4] = fmaxf(fmaf(v1.x, sc[c0 + 4], sh[c0 + 4]), 0.f);
        t[5] = fmaxf(fmaf(v1.y, sc[c0 + 5], sh[c0 + 5]), 0.f);
        t[6] = fmaxf(fmaf(v1.z, sc[c0 + 6], sh[c0 + 6]), 0.f);
        t[7] = fmaxf(fmaf(v1.w, sc[c0 + 7], sh[c0 + 7]), 0.f);
        union { __half2 hh[4]; uint4 u; } cv;
        cv.hh[0] = __floats2half2_rn(t[0], t[1]);
        cv.hh[1] = __floats2half2_rn(t[2], t[3]);
        cv.hh[2] = __floats2half2_rn(t[4], t[5]);
        cv.hh[3] = __floats2half2_rn(t[6], t[7]);
        ((uint4*)out)[i] = cv.u;
    }
}

// ---------------------------------------------------------------------------
// Per-channel stats finalize: scale = gamma*rsqrt(var+eps), shift = beta - mean*scale
// ---------------------------------------------------------------------------
__global__ __launch_bounds__(256)
void finalize_kernel(const float* __restrict__ part,
                     const float* __restrict__ gamma,
                     const float* __restrict__ beta,
                     float*       __restrict__ stats)
{
    const int c   = blockIdx.x;
    const int tid = threadIdx.x;
    float s = 0.f, s2 = 0.f;
    for (int b = tid; b < NBC; b += 256) {
        s  += part[b * (2 * CCH) + c];
        s2 += part[b * (2 * CCH) + CCH + c];
    }
    __shared__ float r1[256], r2[256];
    r1[tid] = s; r2[tid] = s2;
    __syncthreads();
    for (int o = 128; o > 0; o >>= 1) {
        if (tid < o) { r1[tid] += r1[tid + o]; r2[tid] += r2[tid + o]; }
        __syncthreads();
    }
    if (tid == 0) {
        float mean = r1[0] * (1.0f / NP);
        float var  = r2[0] * (1.0f / NP) - mean * mean;
        float istd = rsqrtf(var + EPSV);
        float sc   = istd * gamma[c];
        stats[c]       = sc;
        stats[CCH + c] = beta[c] - mean * sc;
    }
}

// ---------------------------------------------------------------------------
// out = relu( buf2*scale2 + shift2 + feats )
// ---------------------------------------------------------------------------
__global__ __launch_bounds__(256)
void epi_kernel(const float* __restrict__ buf2,
                const float* __restrict__ stats,
                const float* __restrict__ feats,
                float*       __restrict__ out)
{
    __shared__ float sc[CCH], sh[CCH];
    if (threadIdx.x < CCH) {
        sc[threadIdx.x] = stats[threadIdx.x];
        sh[threadIdx.x] = stats[CCH + threadIdx.x];
    }
    __syncthreads();
    int i = blockIdx.x * blockDim.x + threadIdx.x;   // float4 index
    if (i < NP * CCH / 4) {
        float4 v = ((const float4*)buf2)[i];
        float4 f = ((const float4*)feats)[i];
        int c = (i * 4) & 63;
        v.x = fmaxf(fmaf(v.x, sc[c + 0], sh[c + 0]) + f.x, 0.f);
        v.y = fmaxf(fmaf(v.y, sc[c + 1], sh[c + 1]) + f.y, 0.f);
        v.z = fmaxf(fmaf(v.z, sc[c + 2], sh[c + 2]) + f.z, 0.f);
        v.w = fmaxf(fmaf(v.w, sc[c + 3], sh[c + 3]) + f.w, 0.f);
        ((float4*)out)[i] = v;
    }
}

// ---------------------------------------------------------------------------
extern "C" void kernel_launch(void* const* d_in, const int* in_sizes, int n_in,
                              void* d_out, int out_size)
{
    const float* feats  = (const float*)d_in[0];
    const float* W1     = (const float*)d_in[1];
    const float* gamma1 = (const float*)d_in[2];
    const float* beta1  = (const float*)d_in[3];
    const float* W2     = (const float*)d_in[4];
    const float* gamma2 = (const float*)d_in[5];
    const float* beta2  = (const float*)d_in[6];
    const int*   idx1   = (const int*)  d_in[7];
    const float* mask1  = (const float*)d_in[8];
    const int*   idx2   = (const int*)  d_in[9];
    const float* mask2  = (const float*)d_in[10];
    float* out = (float*)d_out;

    float *buf1, *buf2, *part1, *part2, *st1, *st2;
    __half *h0, *h1, *wh1, *wh2;
    cudaGetSymbolAddress((void**)&buf1,  g_buf1);
    cudaGetSymbolAddress((void**)&buf2,  g_buf2);
    cudaGetSymbolAddress((void**)&h0,    g_h0);
    cudaGetSymbolAddress((void**)&h1,    g_h1);
    cudaGetSymbolAddress((void**)&wh1,   g_wh1);
    cudaGetSymbolAddress((void**)&wh2,   g_wh2);
    cudaGetSymbolAddress((void**)&part1, g_part1);
    cudaGetSymbolAddress((void**)&part2, g_part2);
    cudaGetSymbolAddress((void**)&st1,   g_stats1);
    cudaGetSymbolAddress((void**)&st2,   g_stats2);

    cudaFuncSetAttribute(conv_h, cudaFuncAttributeMaxDynamicSharedMemorySize, SMEM_BYTES);

    const int cvt_blocks = (NP * CCH / 8 + 255) / 256;
    prep_w<<<KK, 256>>>(W1, wh1);
    prep_w<<<KK, 256>>>(W2, wh2);
    f2h_kernel<<<cvt_blocks, 256>>>(feats, h0);

    conv_h<<<NBC, 256, SMEM_BYTES>>>(h0, idx1, mask1, wh1, buf1, part1);
    finalize_kernel<<<CCH, 256>>>(part1, gamma1, beta1, st1);
    bnrelu2h_kernel<<<cvt_blocks, 256>>>(buf1, st1, h1);
    conv_h<<<NBC, 256, SMEM_BYTES>>>(h1, idx2, mask2, wh2, buf2, part2);
    finalize_kernel<<<CCH, 256>>>(part2, gamma2, beta2, st2);

    const int epi_blocks = (NP * CCH / 4 + 255) / 256;
    epi_kernel<<<epi_blocks, 256>>>(buf2, st2, feats, out);
}

// round 7
// speedup vs baseline: 4.5420x; 1.1178x over previous
#include <cuda_runtime.h>
#include <cuda_fp16.h>
#include <cstdint>

#define NP     100000
#define CCH    64
#define KK     27
#define EPSV   1e-5f
#define TILE_M 256
#define NBC    ((NP + TILE_M - 1) / TILE_M)   // 391

// ---------------- scratch (device globals; no allocation allowed) ----------------
__device__ float g_buf1[NP * CCH];
__device__ float g_buf2[NP * CCH];
__device__ __align__(16) __half g_h0[NP * CCH];          // half(feats)
__device__ __align__(16) __half g_h1[NP * CCH];          // half(relu(bn1(buf1)))
__device__ __align__(16) __half g_wh1[KK * CCH * CCH];   // Wh[k][d][c] = half(W[k][c][d])
__device__ __align__(16) __half g_wh2[KK * CCH * CCH];
__device__ float g_part1[NBC * 2 * CCH];
__device__ float g_part2[NBC * 2 * CCH];
__device__ float g_stats1[2 * CCH];   // [0:64) scale, [64:128) shift
__device__ float g_stats2[2 * CCH];

// ---------------- PTX helpers ----------------
__device__ __forceinline__ void ldsm4(uint32_t& r0, uint32_t& r1, uint32_t& r2, uint32_t& r3,
                                      uint32_t addr) {
    asm volatile("ldmatrix.sync.aligned.m8n8.x4.shared.b16 {%0,%1,%2,%3}, [%4];"
                 : "=r"(r0), "=r"(r1), "=r"(r2), "=r"(r3) : "r"(addr));
}
__device__ __forceinline__ void mma16816(float* d, uint32_t a0, uint32_t a1, uint32_t a2,
                                         uint32_t a3, uint32_t b0, uint32_t b1) {
    asm volatile(
        "mma.sync.aligned.m16n8k16.row.col.f32.f16.f16.f32 "
        "{%0,%1,%2,%3}, {%4,%5,%6,%7}, {%8,%9}, {%0,%1,%2,%3};"
        : "+f"(d[0]), "+f"(d[1]), "+f"(d[2]), "+f"(d[3])
        : "r"(a0), "r"(a1), "r"(a2), "r"(a3), "r"(b0), "r"(b1));
}
#define CP_ASYNC_Z(dst, src, sz) \
    asm volatile("cp.async.cg.shared.global [%0], [%1], 16, %2;" \
                 :: "r"(dst), "l"(src), "r"(sz) : "memory")
#define CP_ASYNC(dst, src) \
    asm volatile("cp.async.cg.shared.global [%0], [%1], 16;" :: "r"(dst), "l"(src) : "memory")
#define CP_COMMIT()  asm volatile("cp.async.commit_group;" ::: "memory")
#define CP_WAIT1()   asm volatile("cp.async.wait_group 1;" ::: "memory")

// SMEM map (byte offsets from 128-aligned base):
//   A buffers: 3 stages x (256 rows x 128B, SW128)  @ 0      (98304 B)
//   B buffers: 2 stages x ( 64 rows x 128B, SW128)  @ 98304  (16384 B)
//   RED/RED2:  aliased onto B area (epilogue only)  @ 98304 / 100352
#define SM_AB(s)   ((uint32_t)(((s) % 3) * 32768))
#define SM_BB(s)   ((uint32_t)(98304 + ((s) & 1) * 8192))
#define SM_RED     98304
#define SM_RED2    100352
#define SMEM_BYTES (114688 + 128)

// ---------------------------------------------------------------------------
// Sparse conv: dst[n,d] = sum_k sum_c src_h[idx[k,n]][c] * mask[k,n] * Wh[k][d][c]
// fp16 operands, fp32 accum; cp.async pipeline: A gather 3-deep, B (weights) 2-deep.
// Per iter: commit B-group then A-group; wait_group 1 at head => A(k),B(k) resident.
// ---------------------------------------------------------------------------
__global__ __launch_bounds__(256, 2)
void conv_h(const __half* __restrict__ src,
            const int*    __restrict__ idx,
            const float*  __restrict__ mask,
            const __half* __restrict__ Wh,
            float*        __restrict__ dst,
            float*        __restrict__ part)
{
    extern __shared__ char smraw[];
    char* smc = (char*)(((uintptr_t)smraw + 127) & ~(uintptr_t)127);
    uint32_t sb;
    asm("{ .reg .u64 t; cvta.to.shared.u64 t, %1; cvt.u32.u64 %0, t; }" : "=r"(sb) : "l"(smc));
    float* RED  = (float*)(smc + SM_RED);
    float* RED2 = (float*)(smc + SM_RED2);

    const int tid  = threadIdx.x;
    const int w    = tid >> 5;
    const int lane = tid & 31;
    const int n0   = blockIdx.x * TILE_M;
    const int row  = tid;                 // gather row (one full row per thread)
    const int n    = n0 + row;
    const int rs   = row & 7;
    const int gq   = lane >> 2;
    const int tq   = lane & 3;
    const int mrow = lane & 7;
    const int mi   = lane >> 3;

    // loop-invariant LDSM addresses (relative; add buffer base at use)
    uint32_t a_rel[4], b_rel[4];
#pragma unroll
    for (int ks = 0; ks < 4; ++ks) {
        a_rel[ks] = (uint32_t)(w * 32 + (mi & 1) * 8 + mrow) * 128u
                  + (uint32_t)((2 * ks + (mi >> 1)) ^ mrow) * 16u;
        b_rel[ks] = (uint32_t)((mi >> 1) * 8 + mrow) * 128u
                  + (uint32_t)((2 * ks + (mi & 1)) ^ mrow) * 16u;
    }
    // W chunk assignment: chunks 2*tid, 2*tid+1 (16B each)
    const int c16_0 = 2 * tid, c16_1 = 2 * tid + 1;
    const uint32_t wd0 = (uint32_t)(c16_0 >> 3) * 128u + (uint32_t)((c16_0 & 7) ^ ((c16_0 >> 3) & 7)) * 16u;
    const uint32_t wd1 = (uint32_t)(c16_1 >> 3) * 128u + (uint32_t)((c16_1 & 7) ^ ((c16_1 >> 3) & 7)) * 16u;
    const uint32_t arow = (uint32_t)row * 128u;

    // ---- prologue: B(0) | A(0) | A(1) as three groups; prefetch idx/mask(2) ----
    {
        const char* wp = (const char*)Wh;
        uint32_t bbase = sb + SM_BB(0);
        CP_ASYNC(bbase + wd0, wp + c16_0 * 16);
        CP_ASYNC(bbase + wd1, wp + c16_1 * 16);
        CP_COMMIT();
    }
#pragma unroll
    for (int s = 0; s < 2; ++s) {
        int   gi = 0; float mm = 0.f;
        if (n < NP) { gi = idx[(size_t)s * NP + n]; mm = mask[(size_t)s * NP + n]; }
        const char* gp = (const char*)(src + (size_t)gi * CCH);
        uint32_t abase = sb + SM_AB(s) + arow;
        uint32_t sz = (mm != 0.f) ? 16u : 0u;
#pragma unroll
        for (int j = 0; j < 8; ++j)
            CP_ASYNC_Z(abase + (uint32_t)((j ^ rs) * 16), gp + j * 16, sz);
        CP_COMMIT();
    }
    int   idx_c = 0;
    float m_c   = 0.f;
    if (n < NP) { idx_c = idx[(size_t)2 * NP + n]; m_c = mask[(size_t)2 * NP + n]; }

    float acc[2][8][4];
#pragma unroll
    for (int t = 0; t < 2; ++t)
#pragma unroll
        for (int nb = 0; nb < 8; ++nb)
#pragma unroll
            for (int i = 0; i < 4; ++i) acc[t][nb][i] = 0.f;

    for (int k = 0; k < KK; ++k) {
        CP_WAIT1();            // A(k), B(k) resident (only newest group may pend)
        __syncthreads();       // all warps: stage k visible; iter k-1 MMA done

        // ---- issue B(k+1) group (possibly empty) ----
        if (k + 1 < KK) {
            const char* wp = (const char*)(Wh + (size_t)(k + 1) * CCH * CCH);
            uint32_t bbase = sb + SM_BB(k + 1);
            CP_ASYNC(bbase + wd0, wp + c16_0 * 16);
            CP_ASYNC(bbase + wd1, wp + c16_1 * 16);
        }
        CP_COMMIT();
        // ---- issue A(k+2) group (possibly empty) ----
        if (k + 2 < KK) {
            const char* gp = (const char*)(src + (size_t)idx_c * CCH);
            uint32_t abase = sb + SM_AB(k + 2) + arow;
            uint32_t sz = (m_c != 0.f) ? 16u : 0u;
#pragma unroll
            for (int j = 0; j < 8; ++j)
                CP_ASYNC_Z(abase + (uint32_t)((j ^ rs) * 16), gp + j * 16, sz);
        }
        CP_COMMIT();
        // prefetch idx/mask for stage k+3
        idx_c = 0; m_c = 0.f;
        if (k + 3 < KK && n < NP) {
            idx_c = idx[(size_t)(k + 3) * NP + n];
            m_c   = mask[(size_t)(k + 3) * NP + n];
        }

        // ---- MMA on buffers (k%3, k%2): 4 k-steps x (2 m-tiles x 8 n-blocks) ----
        const uint32_t ab = sb + SM_AB(k);
        const uint32_t bb = sb + SM_BB(k);
#pragma unroll
        for (int ks = 0; ks < 4; ++ks) {
            uint32_t a00, a01, a02, a03, a10, a11, a12, a13;
            ldsm4(a00, a01, a02, a03, ab + a_rel[ks]);
            ldsm4(a10, a11, a12, a13, ab + a_rel[ks] + 2048u);   // mtile 1 (+16 rows)
#pragma unroll
            for (int nbp = 0; nbp < 4; ++nbp) {
                uint32_t b0, b1, b2, b3;
                ldsm4(b0, b1, b2, b3, bb + b_rel[ks] + (uint32_t)nbp * 2048u);
                mma16816(acc[0][2 * nbp],     a00, a01, a02, a03, b0, b1);
                mma16816(acc[0][2 * nbp + 1], a00, a01, a02, a03, b2, b3);
                mma16816(acc[1][2 * nbp],     a10, a11, a12, a13, b0, b1);
                mma16816(acc[1][2 * nbp + 1], a10, a11, a12, a13, b2, b3);
            }
        }
        // no trailing bar: next iteration's wait+bar orders buffer reuse
    }
    __syncthreads();   // all MMA done before RED aliases the B area

    // ---- epilogue: direct dst stores + shuffle-reduced BN partials ----
#pragma unroll
    for (int t = 0; t < 2; ++t) {
#pragma unroll
        for (int nb = 0; nb < 8; ++nb) {
            int rlo = n0 + w * 32 + t * 16 + gq;
            if (rlo < NP)
                *(float2*)(dst + (size_t)rlo * CCH + nb * 8 + 2 * tq) =
                    make_float2(acc[t][nb][0], acc[t][nb][1]);
            if (rlo + 8 < NP)
                *(float2*)(dst + (size_t)(rlo + 8) * CCH + nb * 8 + 2 * tq) =
                    make_float2(acc[t][nb][2], acc[t][nb][3]);
        }
    }
    // per-channel sums over this warp's 32 rows; rows >= NP hold exact zeros
#pragma unroll
    for (int cidx = 0; cidx < 16; ++cidx) {
        const int nb = cidx >> 1, j = cidx & 1;
        float p = acc[0][nb][j] + acc[0][nb][2 + j] + acc[1][nb][j] + acc[1][nb][2 + j];
        float q = acc[0][nb][j] * acc[0][nb][j];
        q = fmaf(acc[0][nb][2 + j], acc[0][nb][2 + j], q);
        q = fmaf(acc[1][nb][j],     acc[1][nb][j],     q);
        q = fmaf(acc[1][nb][2 + j], acc[1][nb][2 + j], q);
#pragma unroll
        for (int d = 4; d < 32; d <<= 1) {      // reduce over gq (lanes stride 4)
            p += __shfl_xor_sync(0xFFFFFFFFu, p, d);
            q += __shfl_xor_sync(0xFFFFFFFFu, q, d);
        }
        if (lane < 4) {                          // gq == 0
            RED[w * 64 + nb * 8 + 2 * tq + j]  = p;
            RED2[w * 64 + nb * 8 + 2 * tq + j] = q;
        }
    }
    __syncthreads();
    if (tid < CCH) {
        float s = 0.f, s2 = 0.f;
#pragma unroll
        for (int ww = 0; ww < 8; ++ww) { s += RED[ww * 64 + tid]; s2 += RED2[ww * 64 + tid]; }
        part[blockIdx.x * (2 * CCH) + tid]       = s;
        part[blockIdx.x * (2 * CCH) + CCH + tid] = s2;
    }
}

// ---------------------------------------------------------------------------
// prep: Wh[k][d][c] = half(W[k][c][d])
// ---------------------------------------------------------------------------
__global__ __launch_bounds__(256)
void prep_w(const float* __restrict__ W, __half* __restrict__ Wh)
{
    int k = blockIdx.x;
    const float* Wk = W  + (size_t)k * CCH * CCH;
    __half*      Wo = Wh + (size_t)k * CCH * CCH;
    for (int i = threadIdx.x; i < CCH * CCH; i += 256) {
        int d = i >> 6, c = i & 63;
        Wo[i] = __float2half_rn(Wk[c * CCH + d]);
    }
}

// ---------------------------------------------------------------------------
// feats -> half  (8 elements / thread)
// ---------------------------------------------------------------------------
__global__ __launch_bounds__(256)
void f2h_kernel(const float* __restrict__ in, __half* __restrict__ out)
{
    int i = blockIdx.x * 256 + threadIdx.x;
    if (i < NP * CCH / 8) {
        const float4* p = (const float4*)in + 2 * i;
        float4 v0 = p[0], v1 = p[1];
        union { __half2 hh[4]; uint4 u; } cv;
        cv.hh[0] = __floats2half2_rn(v0.x, v0.y);
        cv.hh[1] = __floats2half2_rn(v0.z, v0.w);
        cv.hh[2] = __floats2half2_rn(v1.x, v1.y);
        cv.hh[3] = __floats2half2_rn(v1.z, v1.w);
        ((uint4*)out)[i] = cv.u;
    }
}

// ---------------------------------------------------------------------------
// h1 = half(relu(buf1*scale1 + shift1))   (8 elements / thread)
// ---------------------------------------------------------------------------
__global__ __launch_bounds__(256)
void bnrelu2h_kernel(const float* __restrict__ in, const float* __restrict__ stats,
                     __half* __restrict__ out)
{
    __shared__ float scsh[128];
    if (threadIdx.x < 128) scsh[threadIdx.x] = stats[threadIdx.x];
    __syncthreads();
    int i = blockIdx.x * 256 + threadIdx.x;
    if (i < NP * CCH / 8) {
        const float4* p = (const float4*)in + 2 * i;
        float4 v0 = p[0], v1 = p[1];
        int c0 = (i * 8) & 63;
        const float* sc = scsh, * sh = scsh + 64;
        float t[8];
        t[0] = fmaxf(fmaf(v0.x, sc[c0 + 0], sh[c0 + 0]), 0.f);
        t[1] = fmaxf(fmaf(v0.y, sc[c0 + 1], sh[c0 + 1]), 0.f);
        t[2] = fmaxf(fmaf(v0.z, sc[c0 + 2], sh[c0 + 2]), 0.f);
        t[3] = fmaxf(fmaf(v0.w, sc[c0 + 3], sh[c0 + 3]), 0.f);
        t[4] = fmaxf(fmaf(v1.x, sc[c0 + 4], sh[c0 + 4]), 0.f);
        t[5] = fmaxf(fmaf(v1.y, sc[c0 + 5], sh[c0 + 5]), 0.f);
        t[6] = fmaxf(fmaf(v1.z, sc[c0 + 6], sh[c0 + 6]), 0.f);
        t[7] = fmaxf(fmaf(v1.w, sc[c0 + 7], sh[c0 + 7]), 0.f);
        union { __half2 hh[4]; uint4 u; } cv;
        cv.hh[0] = __floats2half2_rn(t[0], t[1]);
        cv.hh[1] = __floats2half2_rn(t[2], t[3]);
        cv.hh[2] = __floats2half2_rn(t[4], t[5]);
        cv.hh[3] = __floats2half2_rn(t[6], t[7]);
        ((uint4*)out)[i] = cv.u;
    }
}

// ---------------------------------------------------------------------------
// Per-channel stats finalize: scale = gamma*rsqrt(var+eps), shift = beta - mean*scale
// ---------------------------------------------------------------------------
__global__ __launch_bounds__(256)
void finalize_kernel(const float* __restrict__ part,
                     const float* __restrict__ gamma,
                     const float* __restrict__ beta,
                     float*       __restrict__ stats)
{
    const int c   = blockIdx.x;
    const int tid = threadIdx.x;
    float s = 0.f, s2 = 0.f;
    for (int b = tid; b < NBC; b += 256) {
        s  += part[b * (2 * CCH) + c];
        s2 += part[b * (2 * CCH) + CCH + c];
    }
    __shared__ float r1[256], r2[256];
    r1[tid] = s; r2[tid] = s2;
    __syncthreads();
    for (int o = 128; o > 0; o >>= 1) {
        if (tid < o) { r1[tid] += r1[tid + o]; r2[tid] += r2[tid + o]; }
        __syncthreads();
    }
    if (tid == 0) {
        float mean = r1[0] * (1.0f / NP);
        float var  = r2[0] * (1.0f / NP) - mean * mean;
        float istd = rsqrtf(var + EPSV);
        float sc   = istd * gamma[c];
        stats[c]       = sc;
        stats[CCH + c] = beta[c] - mean * sc;
    }
}

// ---------------------------------------------------------------------------
// out = relu( buf2*scale2 + shift2 + feats )
// ---------------------------------------------------------------------------
__global__ __launch_bounds__(256)
void epi_kernel(const float* __restrict__ buf2,
                const float* __restrict__ stats,
                const float* __restrict__ feats,
                float*       __restrict__ out)
{
    __shared__ float sc[CCH], sh[CCH];
    if (threadIdx.x < CCH) {
        sc[threadIdx.x] = stats[threadIdx.x];
        sh[threadIdx.x] = stats[CCH + threadIdx.x];
    }
    __syncthreads();
    int i = blockIdx.x * blockDim.x + threadIdx.x;   // float4 index
    if (i < NP * CCH / 4) {
        float4 v = ((const float4*)buf2)[i];
        float4 f = ((const float4*)feats)[i];
        int c = (i * 4) & 63;
        v.x = fmaxf(fmaf(v.x, sc[c + 0], sh[c + 0]) + f.x, 0.f);
        v.y = fmaxf(fmaf(v.y, sc[c + 1], sh[c + 1]) + f.y, 0.f);
        v.z = fmaxf(fmaf(v.z, sc[c + 2], sh[c + 2]) + f.z, 0.f);
        v.w = fmaxf(fmaf(v.w, sc[c + 3], sh[c + 3]) + f.w, 0.f);
        ((float4*)out)[i] = v;
    }
}

// ---------------------------------------------------------------------------
extern "C" void kernel_launch(void* const* d_in, const int* in_sizes, int n_in,
                              void* d_out, int out_size)
{
    const float* feats  = (const float*)d_in[0];
    const float* W1     = (const float*)d_in[1];
    const float* gamma1 = (const float*)d_in[2];
    const float* beta1  = (const float*)d_in[3];
    const float* W2     = (const float*)d_in[4];
    const float* gamma2 = (const float*)d_in[5];
    const float* beta2  = (const float*)d_in[6];
    const int*   idx1   = (const int*)  d_in[7];
    const float* mask1  = (const float*)d_in[8];
    const int*   idx2   = (const int*)  d_in[9];
    const float* mask2  = (const float*)d_in[10];
    float* out = (float*)d_out;

    float *buf1, *buf2, *part1, *part2, *st1, *st2;
    __half *h0, *h1, *wh1, *wh2;
    cudaGetSymbolAddress((void**)&buf1,  g_buf1);
    cudaGetSymbolAddress((void**)&buf2,  g_buf2);
    cudaGetSymbolAddress((void**)&h0,    g_h0);
    cudaGetSymbolAddress((void**)&h1,    g_h1);
    cudaGetSymbolAddress((void**)&wh1,   g_wh1);
    cudaGetSymbolAddress((void**)&wh2,   g_wh2);
    cudaGetSymbolAddress((void**)&part1, g_part1);
    cudaGetSymbolAddress((void**)&part2, g_part2);
    cudaGetSymbolAddress((void**)&st1,   g_stats1);
    cudaGetSymbolAddress((void**)&st2,   g_stats2);

    cudaFuncSetAttribute(conv_h, cudaFuncAttributeMaxDynamicSharedMemorySize, SMEM_BYTES);

    const int cvt_blocks = (NP * CCH / 8 + 255) / 256;
    prep_w<<<KK, 256>>>(W1, wh1);
    prep_w<<<KK, 256>>>(W2, wh2);
    f2h_kernel<<<cvt_blocks, 256>>>(feats, h0);

    conv_h<<<NBC, 256, SMEM_BYTES>>>(h0, idx1, mask1, wh1, buf1, part1);
    finalize_kernel<<<CCH, 256>>>(part1, gamma1, beta1, st1);
    bnrelu2h_kernel<<<cvt_blocks, 256>>>(buf1, st1, h1);
    conv_h<<<NBC, 256, SMEM_BYTES>>>(h1, idx2, mask2, wh2, buf2, part2);
    finalize_kernel<<<CCH, 256>>>(part2, gamma2, beta2, st2);

    const int epi_blocks = (NP * CCH / 4 + 255) / 256;
    epi_kernel<<<epi_blocks, 256>>>(buf2, st2, feats, out);
}

// round 8
// speedup vs baseline: 4.9152x; 1.0822x over previous
#include <cuda_runtime.h>
#include <cuda_fp16.h>
#include <cstdint>

#define NP     100000
#define CCH    64
#define KK     27
#define EPSV   1e-5f
#define TILE_M 256
#define NBC    ((NP + TILE_M - 1) / TILE_M)   // 391

// ---------------- scratch (device globals; no allocation allowed) ----------------
__device__ float g_buf1[NP * CCH];
__device__ float g_buf2[NP * CCH];
__device__ __align__(16) __half g_h0[NP * CCH];          // half(feats)
__device__ __align__(16) __half g_h1[NP * CCH];          // half(relu(bn1(buf1)))
__device__ uint4 g_wf1[KK * 512];                        // W1 in mma-fragment order
__device__ uint4 g_wf2[KK * 512];                        // W2 in mma-fragment order
__device__ float g_part1[NBC * 2 * CCH];
__device__ float g_part2[NBC * 2 * CCH];
__device__ float g_stats1[2 * CCH];   // [0:64) scale, [64:128) shift
__device__ float g_stats2[2 * CCH];

// ---------------- PTX helpers ----------------
__device__ __forceinline__ void ldsm4(uint32_t& r0, uint32_t& r1, uint32_t& r2, uint32_t& r3,
                                      uint32_t addr) {
    asm volatile("ldmatrix.sync.aligned.m8n8.x4.shared.b16 {%0,%1,%2,%3}, [%4];"
                 : "=r"(r0), "=r"(r1), "=r"(r2), "=r"(r3) : "r"(addr));
}
__device__ __forceinline__ void mma16816(float* d, uint32_t a0, uint32_t a1, uint32_t a2,
                                         uint32_t a3, uint32_t b0, uint32_t b1) {
    asm volatile(
        "mma.sync.aligned.m16n8k16.row.col.f32.f16.f16.f32 "
        "{%0,%1,%2,%3}, {%4,%5,%6,%7}, {%8,%9}, {%0,%1,%2,%3};"
        : "+f"(d[0]), "+f"(d[1]), "+f"(d[2]), "+f"(d[3])
        : "r"(a0), "r"(a1), "r"(a2), "r"(a3), "r"(b0), "r"(b1));
}
#define CP_ASYNC_Z(dst, src, sz) \
    asm volatile("cp.async.cg.shared.global [%0], [%1], 16, %2;" \
                 :: "r"(dst), "l"(src), "r"(sz) : "memory")
#define CP_COMMIT()  asm volatile("cp.async.commit_group;" ::: "memory")
#define CP_WAIT1()   asm volatile("cp.async.wait_group 1;" ::: "memory")

// SMEM map (byte offsets from 128-aligned base):
//   A buffers: 3 stages x (256 rows x 128B, SW128)  @ 0       (98304 B)
//   RED/RED2:  512 + 512 fp32                       @ 98304 / 100352
#define SM_AB(s)   ((uint32_t)(((s) % 3) * 32768))
#define SM_RED     98304
#define SM_RED2    100352
#define SMEM_BYTES (102400 + 128)

// ---------------------------------------------------------------------------
// Sparse conv: dst[n,d] = sum_k sum_c src_h[idx[k,n]][c] * mask[k,n] * W[k][c][d]
// fp16 operands, fp32 accum. NO CTA barrier in main loop:
//   - A tile is warp-local (warp w owns rows 32w..32w+31): per-warp 3-deep
//     cp.async ring paced by cp.async.wait_group + __syncwarp.
//   - B comes straight from global memory in pre-packed mma-fragment order
//     (coalesced LDG.128, L1-broadcast across warps/CTAs).
// ---------------------------------------------------------------------------
__global__ __launch_bounds__(256, 2)
void conv_h(const __half* __restrict__ src,
            const int*    __restrict__ idx,
            const float*  __restrict__ mask,
            const uint4*  __restrict__ Wf,
            float*        __restrict__ dst,
            float*        __restrict__ part)
{
    extern __shared__ char smraw[];
    char* smc = (char*)(((uintptr_t)smraw + 127) & ~(uintptr_t)127);
    uint32_t sb;
    asm("{ .reg .u64 t; cvta.to.shared.u64 t, %1; cvt.u32.u64 %0, t; }" : "=r"(sb) : "l"(smc));
    float* RED  = (float*)(smc + SM_RED);
    float* RED2 = (float*)(smc + SM_RED2);

    const int tid  = threadIdx.x;
    const int w    = tid >> 5;
    const int lane = tid & 31;
    const int n0   = blockIdx.x * TILE_M;
    const int row  = tid;                 // gather row (one full row per thread)
    const int n    = n0 + row;
    const int rs   = row & 7;
    const int gq   = lane >> 2;
    const int tq   = lane & 3;
    const int mrow = lane & 7;
    const int mi   = lane >> 3;

    // loop-invariant A LDSM addresses (relative; add stage base at use)
    uint32_t a_rel[4];
#pragma unroll
    for (int ks = 0; ks < 4; ++ks)
        a_rel[ks] = (uint32_t)(w * 32 + (mi & 1) * 8 + mrow) * 128u
                  + (uint32_t)((2 * ks + (mi >> 1)) ^ mrow) * 16u;
    const uint32_t arow = (uint32_t)row * 128u;

    // ---- prologue: issue A(0), A(1); prefetch idx/mask for A(2) ----
#pragma unroll
    for (int s = 0; s < 2; ++s) {
        int   gi = 0; float mm = 0.f;
        if (n < NP) { gi = idx[(size_t)s * NP + n]; mm = mask[(size_t)s * NP + n]; }
        const char* gp = (const char*)(src + (size_t)gi * CCH);
        uint32_t abase = sb + SM_AB(s) + arow;
        uint32_t sz = (mm != 0.f) ? 16u : 0u;
#pragma unroll
        for (int j = 0; j < 8; ++j)
            CP_ASYNC_Z(abase + (uint32_t)((j ^ rs) * 16), gp + j * 16, sz);
        CP_COMMIT();
    }
    int   idx_c = 0;
    float m_c   = 0.f;
    if (n < NP) { idx_c = idx[(size_t)2 * NP + n]; m_c = mask[(size_t)2 * NP + n]; }

    float acc[2][8][4];
#pragma unroll
    for (int t = 0; t < 2; ++t)
#pragma unroll
        for (int nb = 0; nb < 8; ++nb)
#pragma unroll
            for (int i = 0; i < 4; ++i) acc[t][nb][i] = 0.f;

    for (int k = 0; k < KK; ++k) {
        CP_WAIT1();            // per-warp: A(k) resident (only A(k+1) may pend)
        __syncwarp();          // order async writes vs this warp's ldsm

        // ---- issue A(k+2) into stage (k+2)%3 (read by this warp in iter k-1,
        //      LDSM read long complete; async write lands >=200cyc later) ----
        if (k + 2 < KK) {
            const char* gp = (const char*)(src + (size_t)idx_c * CCH);
            uint32_t abase = sb + SM_AB(k + 2) + arow;
            uint32_t sz = (m_c != 0.f) ? 16u : 0u;
#pragma unroll
            for (int j = 0; j < 8; ++j)
                CP_ASYNC_Z(abase + (uint32_t)((j ^ rs) * 16), gp + j * 16, sz);
        }
        CP_COMMIT();
        idx_c = 0; m_c = 0.f;
        if (k + 3 < KK && n < NP) {
            idx_c = idx[(size_t)(k + 3) * NP + n];
            m_c   = mask[(size_t)(k + 3) * NP + n];
        }

        // ---- MMA: A via warp-local ldsm, B via fragment-order LDG.128 ----
        const uint32_t ab = sb + SM_AB(k);
        const uint4* wfk = Wf + (size_t)k * 512 + lane;
        uint4 ba = wfk[0];
        uint4 bb = wfk[32];
        uint32_t a00, a01, a02, a03, a10, a11, a12, a13;
#pragma unroll
        for (int i = 0; i < 16; ++i) {
            const int ks = i >> 2, nbp = i & 3;
            if (nbp == 0) {
                ldsm4(a00, a01, a02, a03, ab + a_rel[ks]);
                ldsm4(a10, a11, a12, a13, ab + a_rel[ks] + 2048u);
            }
            uint4 bc = ba;
            ba = bb;
            if (i + 2 < 16) bb = wfk[(size_t)(i + 2) * 32];
            mma16816(acc[0][2 * nbp],     a00, a01, a02, a03, bc.x, bc.y);
            mma16816(acc[0][2 * nbp + 1], a00, a01, a02, a03, bc.z, bc.w);
            mma16816(acc[1][2 * nbp],     a10, a11, a12, a13, bc.x, bc.y);
            mma16816(acc[1][2 * nbp + 1], a10, a11, a12, a13, bc.z, bc.w);
        }
    }

    // ---- epilogue: direct dst stores + shuffle-reduced BN partials ----
#pragma unroll
    for (int t = 0; t < 2; ++t) {
#pragma unroll
        for (int nb = 0; nb < 8; ++nb) {
            int rlo = n0 + w * 32 + t * 16 + gq;
            if (rlo < NP)
                *(float2*)(dst + (size_t)rlo * CCH + nb * 8 + 2 * tq) =
                    make_float2(acc[t][nb][0], acc[t][nb][1]);
            if (rlo + 8 < NP)
                *(float2*)(dst + (size_t)(rlo + 8) * CCH + nb * 8 + 2 * tq) =
                    make_float2(acc[t][nb][2], acc[t][nb][3]);
        }
    }
    // per-channel sums over this warp's 32 rows; rows >= NP hold exact zeros
#pragma unroll
    for (int cidx = 0; cidx < 16; ++cidx) {
        const int nb = cidx >> 1, j = cidx & 1;
        float p = acc[0][nb][j] + acc[0][nb][2 + j] + acc[1][nb][j] + acc[1][nb][2 + j];
        float q = acc[0][nb][j] * acc[0][nb][j];
        q = fmaf(acc[0][nb][2 + j], acc[0][nb][2 + j], q);
        q = fmaf(acc[1][nb][j],     acc[1][nb][j],     q);
        q = fmaf(acc[1][nb][2 + j], acc[1][nb][2 + j], q);
#pragma unroll
        for (int d = 4; d < 32; d <<= 1) {      // reduce over gq (lanes stride 4)
            p += __shfl_xor_sync(0xFFFFFFFFu, p, d);
            q += __shfl_xor_sync(0xFFFFFFFFu, q, d);
        }
        if (lane < 4) {                          // gq == 0
            RED[w * 64 + nb * 8 + 2 * tq + j]  = p;
            RED2[w * 64 + nb * 8 + 2 * tq + j] = q;
        }
    }
    __syncthreads();
    if (tid < CCH) {
        float s = 0.f, s2 = 0.f;
#pragma unroll
        for (int ww = 0; ww < 8; ++ww) { s += RED[ww * 64 + tid]; s2 += RED2[ww * 64 + tid]; }
        part[blockIdx.x * (2 * CCH) + tid]       = s;
        part[blockIdx.x * (2 * CCH) + CCH + tid] = s2;
    }
}

// ---------------------------------------------------------------------------
// prep: pack W[k][c][d] into mma-fragment order.
// Fragment f = ks*4+nbp (ks: k16 step, nbp: n-block pair), lane = gq*4+tq:
//   u.x = {H(c0,  d0), H(c0+1,d0)}    u.y = {H(c0+8,d0),  H(c0+9,d0)}
//   u.z = {H(c0,  d0+8),H(c0+1,d0+8)} u.w = {H(c0+8,d0+8),H(c0+9,d0+8)}
// with c0 = 16*ks + 2*tq, d0 = 16*nbp + gq, H(c,d) = half(W[k][c][d]).
// ---------------------------------------------------------------------------
__global__ __launch_bounds__(512)
void prep_wf(const float* __restrict__ W, uint4* __restrict__ Wf)
{
    const int k    = blockIdx.x;
    const int tid  = threadIdx.x;       // 512 = 16 frags x 32 lanes
    const int lane = tid & 31;
    const int f    = tid >> 5;
    const int ks   = f >> 2, nbp = f & 3;
    const int gq   = lane >> 2, tq = lane & 3;
    const int c0   = 16 * ks + 2 * tq;
    const int d0   = 16 * nbp + gq;
    const float* Wk = W + (size_t)k * CCH * CCH;
    union { __half2 h[4]; uint4 u; } o;
    o.h[0] = __floats2half2_rn(Wk[(c0 + 0) * CCH + d0],     Wk[(c0 + 1) * CCH + d0]);
    o.h[1] = __floats2half2_rn(Wk[(c0 + 8) * CCH + d0],     Wk[(c0 + 9) * CCH + d0]);
    o.h[2] = __floats2half2_rn(Wk[(c0 + 0) * CCH + d0 + 8], Wk[(c0 + 1) * CCH + d0 + 8]);
    o.h[3] = __floats2half2_rn(Wk[(c0 + 8) * CCH + d0 + 8], Wk[(c0 + 9) * CCH + d0 + 8]);
    Wf[(size_t)k * 512 + f * 32 + lane] = o.u;
}

// ---------------------------------------------------------------------------
// feats -> half  (8 elements / thread)
// ---------------------------------------------------------------------------
__global__ __launch_bounds__(256)
void f2h_kernel(const float* __restrict__ in, __half* __restrict__ out)
{
    int i = blockIdx.x * 256 + threadIdx.x;
    if (i < NP * CCH / 8) {
        const float4* p = (const float4*)in + 2 * i;
        float4 v0 = p[0], v1 = p[1];
        union { __half2 hh[4]; uint4 u; } cv;
        cv.hh[0] = __floats2half2_rn(v0.x, v0.y);
        cv.hh[1] = __floats2half2_rn(v0.z, v0.w);
        cv.hh[2] = __floats2half2_rn(v1.x, v1.y);
        cv.hh[3] = __floats2half2_rn(v1.z, v1.w);
        ((uint4*)out)[i] = cv.u;
    }
}

// ---------------------------------------------------------------------------
// h1 = half(relu(buf1*scale1 + shift1))   (8 elements / thread)
// ---------------------------------------------------------------------------
__global__ __launch_bounds__(256)
void bnrelu2h_kernel(const float* __restrict__ in, const float* __restrict__ stats,
                     __half* __restrict__ out)
{
    __shared__ float scsh[128];
    if (threadIdx.x < 128) scsh[threadIdx.x] = stats[threadIdx.x];
    __syncthreads();
    int i = blockIdx.x * 256 + threadIdx.x;
    if (i < NP * CCH / 8) {
        const float4* p = (const float4*)in + 2 * i;
        float4 v0 = p[0], v1 = p[1];
        int c0 = (i * 8) & 63;
        const float* sc = scsh, * sh = scsh + 64;
        float t[8];
        t[0] = fmaxf(fmaf(v0.x, sc[c0 + 0], sh[c0 + 0]), 0.f);
        t[1] = fmaxf(fmaf(v0.y, sc[c0 + 1], sh[c0 + 1]), 0.f);
        t[2] = fmaxf(fmaf(v0.z, sc[c0 + 2], sh[c0 + 2]), 0.f);
        t[3] = fmaxf(fmaf(v0.w, sc[c0 + 3], sh[c0 + 3]), 0.f);
        t[4] = fmaxf(fmaf(v1.x, sc[c0 + 4], sh[c0 + 4]), 0.f);
        t[5] = fmaxf(fmaf(v1.y, sc[c0 + 5], sh[c0 + 5]), 0.f);
        t[6] = fmaxf(fmaf(v1.z, sc[c0 + 6], sh[c0 + 6]), 0.f);
        t[7] = fmaxf(fmaf(v1.w, sc[c0 + 7], sh[c0 + 7]), 0.f);
        union { __half2 hh[4]; uint4 u; } cv;
        cv.hh[0] = __floats2half2_rn(t[0], t[1]);
        cv.hh[1] = __floats2half2_rn(t[2], t[3]);
        cv.hh[2] = __floats2half2_rn(t[4], t[5]);
        cv.hh[3] = __floats2half2_rn(t[6], t[7]);
        ((uint4*)out)[i] = cv.u;
    }
}

// ---------------------------------------------------------------------------
// Per-channel stats finalize: scale = gamma*rsqrt(var+eps), shift = beta - mean*scale
// ---------------------------------------------------------------------------
__global__ __launch_bounds__(256)
void finalize_kernel(const float* __restrict__ part,
                     const float* __restrict__ gamma,
                     const float* __restrict__ beta,
                     float*       __restrict__ stats)
{
    const int c   = blockIdx.x;
    const int tid = threadIdx.x;
    float s = 0.f, s2 = 0.f;
    for (int b = tid; b < NBC; b += 256) {
        s  += part[b * (2 * CCH) + c];
        s2 += part[b * (2 * CCH) + CCH + c];
    }
    __shared__ float r1[256], r2[256];
    r1[tid] = s; r2[tid] = s2;
    __syncthreads();
    for (int o = 128; o > 0; o >>= 1) {
        if (tid < o) { r1[tid] += r1[tid + o]; r2[tid] += r2[tid + o]; }
        __syncthreads();
    }
    if (tid == 0) {
        float mean = r1[0] * (1.0f / NP);
        float var  = r2[0] * (1.0f / NP) - mean * mean;
        float istd = rsqrtf(var + EPSV);
        float sc   = istd * gamma[c];
        stats[c]       = sc;
        stats[CCH + c] = beta[c] - mean * sc;
    }
}

// ---------------------------------------------------------------------------
// out = relu( buf2*scale2 + shift2 + feats )
// ---------------------------------------------------------------------------
__global__ __launch_bounds__(256)
void epi_kernel(const float* __restrict__ buf2,
                const float* __restrict__ stats,
                const float* __restrict__ feats,
                float*       __restrict__ out)
{
    __shared__ float sc[CCH], sh[CCH];
    if (threadIdx.x < CCH) {
        sc[threadIdx.x] = stats[threadIdx.x];
        sh[threadIdx.x] = stats[CCH + threadIdx.x];
    }
    __syncthreads();
    int i = blockIdx.x * blockDim.x + threadIdx.x;   // float4 index
    if (i < NP * CCH / 4) {
        float4 v = ((const float4*)buf2)[i];
        float4 f = ((const float4*)feats)[i];
        int c = (i * 4) & 63;
        v.x = fmaxf(fmaf(v.x, sc[c + 0], sh[c + 0]) + f.x, 0.f);
        v.y = fmaxf(fmaf(v.y, sc[c + 1], sh[c + 1]) + f.y, 0.f);
        v.z = fmaxf(fmaf(v.z, sc[c + 2], sh[c + 2]) + f.z, 0.f);
        v.w = fmaxf(fmaf(v.w, sc[c + 3], sh[c + 3]) + f.w, 0.f);
        ((float4*)out)[i] = v;
    }
}

// ---------------------------------------------------------------------------
extern "C" void kernel_launch(void* const* d_in, const int* in_sizes, int n_in,
                              void* d_out, int out_size)
{
    const float* feats  = (const float*)d_in[0];
    const float* W1     = (const float*)d_in[1];
    const float* gamma1 = (const float*)d_in[2];
    const float* beta1  = (const float*)d_in[3];
    const float* W2     = (const float*)d_in[4];
    const float* gamma2 = (const float*)d_in[5];
    const float* beta2  = (const float*)d_in[6];
    const int*   idx1   = (const int*)  d_in[7];
    const float* mask1  = (const float*)d_in[8];
    const int*   idx2   = (const int*)  d_in[9];
    const float* mask2  = (const float*)d_in[10];
    float* out = (float*)d_out;

    float *buf1, *buf2, *part1, *part2, *st1, *st2;
    __half *h0, *h1;
    uint4 *wf1, *wf2;
    cudaGetSymbolAddress((void**)&buf1,  g_buf1);
    cudaGetSymbolAddress((void**)&buf2,  g_buf2);
    cudaGetSymbolAddress((void**)&h0,    g_h0);
    cudaGetSymbolAddress((void**)&h1,    g_h1);
    cudaGetSymbolAddress((void**)&wf1,   g_wf1);
    cudaGetSymbolAddress((void**)&wf2,   g_wf2);
    cudaGetSymbolAddress((void**)&part1, g_part1);
    cudaGetSymbolAddress((void**)&part2, g_part2);
    cudaGetSymbolAddress((void**)&st1,   g_stats1);
    cudaGetSymbolAddress((void**)&st2,   g_stats2);

    cudaFuncSetAttribute(conv_h, cudaFuncAttributeMaxDynamicSharedMemorySize, SMEM_BYTES);

    const int cvt_blocks = (NP * CCH / 8 + 255) / 256;
    prep_wf<<<KK, 512>>>(W1, wf1);
    prep_wf<<<KK, 512>>>(W2, wf2);
    f2h_kernel<<<cvt_blocks, 256>>>(feats, h0);

    conv_h<<<NBC, 256, SMEM_BYTES>>>(h0, idx1, mask1, wf1, buf1, part1);
    finalize_kernel<<<CCH, 256>>>(part1, gamma1, beta1, st1);
    bnrelu2h_kernel<<<cvt_blocks, 256>>>(buf1, st1, h1);
    conv_h<<<NBC, 256, SMEM_BYTES>>>(h1, idx2, mask2, wf2, buf2, part2);
    finalize_kernel<<<CCH, 256>>>(part2, gamma2, beta2, st2);

    const int epi_blocks = (NP * CCH / 4 + 255) / 256;
    epi_kernel<<<epi_blocks, 256>>>(buf2, st2, feats, out);
}

// round 9
// speedup vs baseline: 4.9340x; 1.0038x over previous
#include <cuda_runtime.h>
#include <cuda_fp16.h>
#include <cstdint>

#define NP     100000
#define CCH    64
#define KK     27
#define EPSV   1e-5f
#define TILE_M 128
#define NBC    ((NP + TILE_M - 1) / TILE_M)   // 782

// ---------------- scratch (device globals; no allocation allowed) ----------------
__device__ float g_buf1[NP * CCH];
__device__ float g_buf2[NP * CCH];
__device__ __align__(16) __half g_h0[NP * CCH];          // half(feats)
__device__ __align__(16) __half g_h1[NP * CCH];          // half(relu(bn1(buf1)))
__device__ uint4 g_wf1[KK * 512];                        // W1 in mma-fragment order
__device__ uint4 g_wf2[KK * 512];                        // W2 in mma-fragment order
__device__ float g_part1[NBC * 2 * CCH];
__device__ float g_part2[NBC * 2 * CCH];
__device__ float g_stats1[2 * CCH];   // [0:64) scale, [64:128) shift
__device__ float g_stats2[2 * CCH];

// ---------------- PTX helpers ----------------
__device__ __forceinline__ void ldsm4(uint32_t& r0, uint32_t& r1, uint32_t& r2, uint32_t& r3,
                                      uint32_t addr) {
    asm volatile("ldmatrix.sync.aligned.m8n8.x4.shared.b16 {%0,%1,%2,%3}, [%4];"
                 : "=r"(r0), "=r"(r1), "=r"(r2), "=r"(r3) : "r"(addr));
}
__device__ __forceinline__ void mma16816(float* d, uint32_t a0, uint32_t a1, uint32_t a2,
                                         uint32_t a3, uint32_t b0, uint32_t b1) {
    asm volatile(
        "mma.sync.aligned.m16n8k16.row.col.f32.f16.f16.f32 "
        "{%0,%1,%2,%3}, {%4,%5,%6,%7}, {%8,%9}, {%0,%1,%2,%3};"
        : "+f"(d[0]), "+f"(d[1]), "+f"(d[2]), "+f"(d[3])
        : "r"(a0), "r"(a1), "r"(a2), "r"(a3), "r"(b0), "r"(b1));
}
#define CP_ASYNC_Z(dst, src, sz) \
    asm volatile("cp.async.cg.shared.global [%0], [%1], 16, %2;" \
                 :: "r"(dst), "l"(src), "r"(sz) : "memory")
#define CP_COMMIT()  asm volatile("cp.async.commit_group;" ::: "memory")
#define CP_WAIT1()   asm volatile("cp.async.wait_group 1;" ::: "memory")

// SMEM map (byte offsets from 128-aligned base):
//   A buffers: 3 stages x (128 rows x 128B, SW128)  @ 0       (49152 B)
//   RED/RED2:  256 + 256 fp32                       @ 49152 / 50176
#define SM_AB(s)   ((uint32_t)(((s) % 3) * 16384))
#define SM_RED     49152
#define SM_RED2    50176
#define SMEM_BYTES (51200 + 128)

// ---------------------------------------------------------------------------
// Sparse conv: dst[n,d] = sum_k sum_c src_h[idx[k,n]][c] * mask[k,n] * W[k][c][d]
// fp16 operands, fp32 accum. 128-thread CTA (4 warps, 128 rows) for fine-grain
// wave scheduling; no CTA barrier in main loop:
//   - A tile warp-local: per-warp 3-deep cp.async ring (wait_group + syncwarp)
//   - B straight from global in pre-packed mma-fragment order (L1 broadcast)
// ---------------------------------------------------------------------------
__global__ __launch_bounds__(128, 4)
void conv_h(const __half* __restrict__ src,
            const int*    __restrict__ idx,
            const float*  __restrict__ mask,
            const uint4*  __restrict__ Wf,
            float*        __restrict__ dst,
            float*        __restrict__ part)
{
    extern __shared__ char smraw[];
    char* smc = (char*)(((uintptr_t)smraw + 127) & ~(uintptr_t)127);
    uint32_t sb;
    asm("{ .reg .u64 t; cvta.to.shared.u64 t, %1; cvt.u32.u64 %0, t; }" : "=r"(sb) : "l"(smc));
    float* RED  = (float*)(smc + SM_RED);
    float* RED2 = (float*)(smc + SM_RED2);

    const int tid  = threadIdx.x;
    const int w    = tid >> 5;
    const int lane = tid & 31;
    const int n0   = blockIdx.x * TILE_M;
    const int row  = tid;                 // gather row (one full row per thread)
    const int n    = n0 + row;
    const int rs   = row & 7;
    const int gq   = lane >> 2;
    const int tq   = lane & 3;
    const int mrow = lane & 7;
    const int mi   = lane >> 3;

    // loop-invariant A LDSM addresses (relative; add stage base at use)
    uint32_t a_rel[4];
#pragma unroll
    for (int ks = 0; ks < 4; ++ks)
        a_rel[ks] = (uint32_t)(w * 32 + (mi & 1) * 8 + mrow) * 128u
                  + (uint32_t)((2 * ks + (mi >> 1)) ^ mrow) * 16u;
    const uint32_t arow = (uint32_t)row * 128u;

    // ---- prologue: issue A(0), A(1); prefetch idx/mask for A(2) ----
#pragma unroll
    for (int s = 0; s < 2; ++s) {
        int   gi = 0; float mm = 0.f;
        if (n < NP) { gi = idx[(size_t)s * NP + n]; mm = mask[(size_t)s * NP + n]; }
        const char* gp = (const char*)(src + (size_t)gi * CCH);
        uint32_t abase = sb + SM_AB(s) + arow;
        uint32_t sz = (mm != 0.f) ? 16u : 0u;
#pragma unroll
        for (int j = 0; j < 8; ++j)
            CP_ASYNC_Z(abase + (uint32_t)((j ^ rs) * 16), gp + j * 16, sz);
        CP_COMMIT();
    }
    int   idx_c = 0;
    float m_c   = 0.f;
    if (n < NP) { idx_c = idx[(size_t)2 * NP + n]; m_c = mask[(size_t)2 * NP + n]; }

    float acc[2][8][4];
#pragma unroll
    for (int t = 0; t < 2; ++t)
#pragma unroll
        for (int nb = 0; nb < 8; ++nb)
#pragma unroll
            for (int i = 0; i < 4; ++i) acc[t][nb][i] = 0.f;

    for (int k = 0; k < KK; ++k) {
        CP_WAIT1();            // per-warp: A(k) resident (only A(k+1) may pend)
        __syncwarp();          // order async writes vs this warp's ldsm

        // ---- issue A(k+2) into stage (k+2)%3 ----
        if (k + 2 < KK) {
            const char* gp = (const char*)(src + (size_t)idx_c * CCH);
            uint32_t abase = sb + SM_AB(k + 2) + arow;
            uint32_t sz = (m_c != 0.f) ? 16u : 0u;
#pragma unroll
            for (int j = 0; j < 8; ++j)
                CP_ASYNC_Z(abase + (uint32_t)((j ^ rs) * 16), gp + j * 16, sz);
        }
        CP_COMMIT();
        idx_c = 0; m_c = 0.f;
        if (k + 3 < KK && n < NP) {
            idx_c = idx[(size_t)(k + 3) * NP + n];
            m_c   = mask[(size_t)(k + 3) * NP + n];
        }

        // ---- MMA: A via warp-local ldsm, B via fragment-order LDG.128 ----
        const uint32_t ab = sb + SM_AB(k);
        const uint4* wfk = Wf + (size_t)k * 512 + lane;
        uint4 ba = wfk[0];
        uint4 bb = wfk[32];
        uint32_t a00, a01, a02, a03, a10, a11, a12, a13;
#pragma unroll
        for (int i = 0; i < 16; ++i) {
            const int ks = i >> 2, nbp = i & 3;
            if (nbp == 0) {
                ldsm4(a00, a01, a02, a03, ab + a_rel[ks]);
                ldsm4(a10, a11, a12, a13, ab + a_rel[ks] + 2048u);
            }
            uint4 bc = ba;
            ba = bb;
            if (i + 2 < 16) bb = wfk[(size_t)(i + 2) * 32];
            mma16816(acc[0][2 * nbp],     a00, a01, a02, a03, bc.x, bc.y);
            mma16816(acc[0][2 * nbp + 1], a00, a01, a02, a03, bc.z, bc.w);
            mma16816(acc[1][2 * nbp],     a10, a11, a12, a13, bc.x, bc.y);
            mma16816(acc[1][2 * nbp + 1], a10, a11, a12, a13, bc.z, bc.w);
        }
    }

    // ---- epilogue: direct dst stores + shuffle-reduced BN partials ----
#pragma unroll
    for (int t = 0; t < 2; ++t) {
#pragma unroll
        for (int nb = 0; nb < 8; ++nb) {
            int rlo = n0 + w * 32 + t * 16 + gq;
            if (rlo < NP)
                *(float2*)(dst + (size_t)rlo * CCH + nb * 8 + 2 * tq) =
                    make_float2(acc[t][nb][0], acc[t][nb][1]);
            if (rlo + 8 < NP)
                *(float2*)(dst + (size_t)(rlo + 8) * CCH + nb * 8 + 2 * tq) =
                    make_float2(acc[t][nb][2], acc[t][nb][3]);
        }
    }
    // per-channel sums over this warp's 32 rows; rows >= NP hold exact zeros
#pragma unroll
    for (int cidx = 0; cidx < 16; ++cidx) {
        const int nb = cidx >> 1, j = cidx & 1;
        float p = acc[0][nb][j] + acc[0][nb][2 + j] + acc[1][nb][j] + acc[1][nb][2 + j];
        float q = acc[0][nb][j] * acc[0][nb][j];
        q = fmaf(acc[0][nb][2 + j], acc[0][nb][2 + j], q);
        q = fmaf(acc[1][nb][j],     acc[1][nb][j],     q);
        q = fmaf(acc[1][nb][2 + j], acc[1][nb][2 + j], q);
#pragma unroll
        for (int d = 4; d < 32; d <<= 1) {      // reduce over gq (lanes stride 4)
            p += __shfl_xor_sync(0xFFFFFFFFu, p, d);
            q += __shfl_xor_sync(0xFFFFFFFFu, q, d);
        }
        if (lane < 4) {                          // gq == 0
            RED[w * 64 + nb * 8 + 2 * tq + j]  = p;
            RED2[w * 64 + nb * 8 + 2 * tq + j] = q;
        }
    }
    __syncthreads();
    if (tid < CCH) {
        float s = 0.f, s2 = 0.f;
#pragma unroll
        for (int ww = 0; ww < 4; ++ww) { s += RED[ww * 64 + tid]; s2 += RED2[ww * 64 + tid]; }
        part[blockIdx.x * (2 * CCH) + tid]       = s;
        part[blockIdx.x * (2 * CCH) + CCH + tid] = s2;
    }
}

// ---------------------------------------------------------------------------
// prep: pack W[k][c][d] into mma-fragment order (lane = gq*4+tq, frag = ks*4+nbp)
// ---------------------------------------------------------------------------
__global__ __launch_bounds__(512)
void prep_wf(const float* __restrict__ W, uint4* __restrict__ Wf)
{
    const int k    = blockIdx.x;
    const int tid  = threadIdx.x;       // 512 = 16 frags x 32 lanes
    const int lane = tid & 31;
    const int f    = tid >> 5;
    const int ks   = f >> 2, nbp = f & 3;
    const int gq   = lane >> 2, tq = lane & 3;
    const int c0   = 16 * ks + 2 * tq;
    const int d0   = 16 * nbp + gq;
    const float* Wk = W + (size_t)k * CCH * CCH;
    union { __half2 h[4]; uint4 u; } o;
    o.h[0] = __floats2half2_rn(Wk[(c0 + 0) * CCH + d0],     Wk[(c0 + 1) * CCH + d0]);
    o.h[1] = __floats2half2_rn(Wk[(c0 + 8) * CCH + d0],     Wk[(c0 + 9) * CCH + d0]);
    o.h[2] = __floats2half2_rn(Wk[(c0 + 0) * CCH + d0 + 8], Wk[(c0 + 1) * CCH + d0 + 8]);
    o.h[3] = __floats2half2_rn(Wk[(c0 + 8) * CCH + d0 + 8], Wk[(c0 + 9) * CCH + d0 + 8]);
    Wf[(size_t)k * 512 + f * 32 + lane] = o.u;
}

// ---------------------------------------------------------------------------
// feats -> half  (8 elements / thread)
// ---------------------------------------------------------------------------
__global__ __launch_bounds__(256)
void f2h_kernel(const float* __restrict__ in, __half* __restrict__ out)
{
    int i = blockIdx.x * 256 + threadIdx.x;
    if (i < NP * CCH / 8) {
        const float4* p = (const float4*)in + 2 * i;
        float4 v0 = p[0], v1 = p[1];
        union { __half2 hh[4]; uint4 u; } cv;
        cv.hh[0] = __floats2half2_rn(v0.x, v0.y);
        cv.hh[1] = __floats2half2_rn(v0.z, v0.w);
        cv.hh[2] = __floats2half2_rn(v1.x, v1.y);
        cv.hh[3] = __floats2half2_rn(v1.z, v1.w);
        ((uint4*)out)[i] = cv.u;
    }
}

// ---------------------------------------------------------------------------
// h1 = half(relu(buf1*scale1 + shift1))   (8 elements / thread)
// ---------------------------------------------------------------------------
__global__ __launch_bounds__(256)
void bnrelu2h_kernel(const float* __restrict__ in, const float* __restrict__ stats,
                     __half* __restrict__ out)
{
    __shared__ float scsh[128];
    if (threadIdx.x < 128) scsh[threadIdx.x] = stats[threadIdx.x];
    __syncthreads();
    int i = blockIdx.x * 256 + threadIdx.x;
    if (i < NP * CCH / 8) {
        const float4* p = (const float4*)in + 2 * i;
        float4 v0 = p[0], v1 = p[1];
        int c0 = (i * 8) & 63;
        const float* sc = scsh, * sh = scsh + 64;
        float t[8];
        t[0] = fmaxf(fmaf(v0.x, sc[c0 + 0], sh[c0 + 0]), 0.f);
        t[1] = fmaxf(fmaf(v0.y, sc[c0 + 1], sh[c0 + 1]), 0.f);
        t[2] = fmaxf(fmaf(v0.z, sc[c0 + 2], sh[c0 + 2]), 0.f);
        t[3] = fmaxf(fmaf(v0.w, sc[c0 + 3], sh[c0 + 3]), 0.f);
        t[4] = fmaxf(fmaf(v1.x, sc[c0 + 4], sh[c0 + 4]), 0.f);
        t[5] = fmaxf(fmaf(v1.y, sc[c0 + 5], sh[c0 + 5]), 0.f);
        t[6] = fmaxf(fmaf(v1.z, sc[c0 + 6], sh[c0 + 6]), 0.f);
        t[7] = fmaxf(fmaf(v1.w, sc[c0 + 7], sh[c0 + 7]), 0.f);
        union { __half2 hh[4]; uint4 u; } cv;
        cv.hh[0] = __floats2half2_rn(t[0], t[1]);
        cv.hh[1] = __floats2half2_rn(t[2], t[3]);
        cv.hh[2] = __floats2half2_rn(t[4], t[5]);
        cv.hh[3] = __floats2half2_rn(t[6], t[7]);
        ((uint4*)out)[i] = cv.u;
    }
}

// ---------------------------------------------------------------------------
// Per-channel stats finalize: scale = gamma*rsqrt(var+eps), shift = beta - mean*scale
// ---------------------------------------------------------------------------
__global__ __launch_bounds__(256)
void finalize_kernel(const float* __restrict__ part,
                     const float* __restrict__ gamma,
                     const float* __restrict__ beta,
                     float*       __restrict__ stats)
{
    const int c   = blockIdx.x;
    const int tid = threadIdx.x;
    float s = 0.f, s2 = 0.f;
    for (int b = tid; b < NBC; b += 256) {
        s  += part[b * (2 * CCH) + c];
        s2 += part[b * (2 * CCH) + CCH + c];
    }
    __shared__ float r1[256], r2[256];
    r1[tid] = s; r2[tid] = s2;
    __syncthreads();
    for (int o = 128; o > 0; o >>= 1) {
        if (tid < o) { r1[tid] += r1[tid + o]; r2[tid] += r2[tid + o]; }
        __syncthreads();
    }
    if (tid == 0) {
        float mean = r1[0] * (1.0f / NP);
        float var  = r2[0] * (1.0f / NP) - mean * mean;
        float istd = rsqrtf(var + EPSV);
        float sc   = istd * gamma[c];
        stats[c]       = sc;
        stats[CCH + c] = beta[c] - mean * sc;
    }
}

// ---------------------------------------------------------------------------
// out = relu( buf2*scale2 + shift2 + feats )
// ---------------------------------------------------------------------------
__global__ __launch_bounds__(256)
void epi_kernel(const float* __restrict__ buf2,
                const float* __restrict__ stats,
                const float* __restrict__ feats,
                float*       __restrict__ out)
{
    __shared__ float sc[CCH], sh[CCH];
    if (threadIdx.x < CCH) {
        sc[threadIdx.x] = stats[threadIdx.x];
        sh[threadIdx.x] = stats[CCH + threadIdx.x];
    }
    __syncthreads();
    int i = blockIdx.x * blockDim.x + threadIdx.x;   // float4 index
    if (i < NP * CCH / 4) {
        float4 v = ((const float4*)buf2)[i];
        float4 f = ((const float4*)feats)[i];
        int c = (i * 4) & 63;
        v.x = fmaxf(fmaf(v.x, sc[c + 0], sh[c + 0]) + f.x, 0.f);
        v.y = fmaxf(fmaf(v.y, sc[c + 1], sh[c + 1]) + f.y, 0.f);
        v.z = fmaxf(fmaf(v.z, sc[c + 2], sh[c + 2]) + f.z, 0.f);
        v.w = fmaxf(fmaf(v.w, sc[c + 3], sh[c + 3]) + f.w, 0.f);
        ((float4*)out)[i] = v;
    }
}

// ---------------------------------------------------------------------------
extern "C" void kernel_launch(void* const* d_in, const int* in_sizes, int n_in,
                              void* d_out, int out_size)
{
    const float* feats  = (const float*)d_in[0];
    const float* W1     = (const float*)d_in[1];
    const float* gamma1 = (const float*)d_in[2];
    const float* beta1  = (const float*)d_in[3];
    const float* W2     = (const float*)d_in[4];
    const float* gamma2 = (const float*)d_in[5];
    const float* beta2  = (const float*)d_in[6];
    const int*   idx1   = (const int*)  d_in[7];
    const float* mask1  = (const float*)d_in[8];
    const int*   idx2   = (const int*)  d_in[9];
    const float* mask2  = (const float*)d_in[10];
    float* out = (float*)d_out;

    float *buf1, *buf2, *part1, *part2, *st1, *st2;
    __half *h0, *h1;
    uint4 *wf1, *wf2;
    cudaGetSymbolAddress((void**)&buf1,  g_buf1);
    cudaGetSymbolAddress((void**)&buf2,  g_buf2);
    cudaGetSymbolAddress((void**)&h0,    g_h0);
    cudaGetSymbolAddress((void**)&h1,    g_h1);
    cudaGetSymbolAddress((void**)&wf1,   g_wf1);
    cudaGetSymbolAddress((void**)&wf2,   g_wf2);
    cudaGetSymbolAddress((void**)&part1, g_part1);
    cudaGetSymbolAddress((void**)&part2, g_part2);
    cudaGetSymbolAddress((void**)&st1,   g_stats1);
    cudaGetSymbolAddress((void**)&st2,   g_stats2);

    cudaFuncSetAttribute(conv_h, cudaFuncAttributeMaxDynamicSharedMemorySize, SMEM_BYTES);

    const int cvt_blocks = (NP * CCH / 8 + 255) / 256;
    prep_wf<<<KK, 512>>>(W1, wf1);
    prep_wf<<<KK, 512>>>(W2, wf2);
    f2h_kernel<<<cvt_blocks, 256>>>(feats, h0);

    conv_h<<<NBC, 128, SMEM_BYTES>>>(h0, idx1, mask1, wf1, buf1, part1);
    finalize_kernel<<<CCH, 256>>>(part1, gamma1, beta1, st1);
    bnrelu2h_kernel<<<cvt_blocks, 256>>>(buf1, st1, h1);
    conv_h<<<NBC, 128, SMEM_BYTES>>>(h1, idx2, mask2, wf2, buf2, part2);
    finalize_kernel<<<CCH, 256>>>(part2, gamma2, beta2, st2);

    const int epi_blocks = (NP * CCH / 4 + 255) / 256;
    epi_kernel<<<epi_blocks, 256>>>(buf2, st2, feats, out);
}

// round 10
// speedup vs baseline: 5.8306x; 1.1817x over previous
#include <cuda_runtime.h>
#include <cuda_fp16.h>
#include <cstdint>

#define NP     100000
#define CCH    64
#define KK     27
#define EPSV   1e-5f
#define TILE_M 128
#define NBC    ((NP + TILE_M - 1) / TILE_M)   // 782

// ---------------- scratch (device globals; no allocation allowed) ----------------
__device__ float g_buf1[NP * CCH];
__device__ float g_buf2[NP * CCH];
__device__ __align__(16) __half g_h0[NP * CCH];          // half(feats)
__device__ __align__(16) __half g_h1[NP * CCH];          // half(relu(bn1(buf1)))
__device__ uint4 g_wf1[KK * 512];                        // W1 in mma-fragment order
__device__ uint4 g_wf2[KK * 512];                        // W2 in mma-fragment order
__device__ float g_part1[NBC * 2 * CCH];
__device__ float g_part2[NBC * 2 * CCH];
__device__ float g_stats1[2 * CCH];   // [0:64) scale, [64:128) shift
__device__ float g_stats2[2 * CCH];

// ---------------- PTX helpers ----------------
__device__ __forceinline__ void ldsm4(uint32_t& r0, uint32_t& r1, uint32_t& r2, uint32_t& r3,
                                      uint32_t addr) {
    asm volatile("ldmatrix.sync.aligned.m8n8.x4.shared.b16 {%0,%1,%2,%3}, [%4];"
                 : "=r"(r0), "=r"(r1), "=r"(r2), "=r"(r3) : "r"(addr));
}
__device__ __forceinline__ void mma16816(float* d, uint32_t a0, uint32_t a1, uint32_t a2,
                                         uint32_t a3, uint32_t b0, uint32_t b1) {
    asm volatile(
        "mma.sync.aligned.m16n8k16.row.col.f32.f16.f16.f32 "
        "{%0,%1,%2,%3}, {%4,%5,%6,%7}, {%8,%9}, {%0,%1,%2,%3};"
        : "+f"(d[0]), "+f"(d[1]), "+f"(d[2]), "+f"(d[3])
        : "r"(a0), "r"(a1), "r"(a2), "r"(a3), "r"(b0), "r"(b1));
}
#define CP_ASYNC_Z(dst, src, sz) \
    asm volatile("cp.async.cg.shared.global [%0], [%1], 16, %2;" \
                 :: "r"(dst), "l"(src), "r"(sz) : "memory")
#define CP_COMMIT()  asm volatile("cp.async.commit_group;" ::: "memory")
#define CP_WAIT1()   asm volatile("cp.async.wait_group 1;" ::: "memory")

// SMEM map (byte offsets from 128-aligned base):
//   A buffers: 3 stages x (128 rows x 128B, SW128)  @ 0       (49152 B)
//   RED/RED2:  256 + 256 fp32                       @ 49152 / 50176
#define SM_AB(s)   ((uint32_t)(((s) % 3) * 16384))
#define SM_RED     49152
#define SM_RED2    50176
#define SMEM_BYTES (51200 + 128)

// ---------------------------------------------------------------------------
// Sparse conv: dst[n,d] = sum_k sum_c src_h[idx[k,n]][c] * mask[k,n] * W[k][c][d]
// fp16 operands, fp32 accum; no CTA barrier in main loop.
// Gather is DIVERGENCE-FREE: each cp.async warp-instruction covers 4 complete
// rows (8 lanes x 16B = one 128B line per row); row idx/mask distributed by
// __shfl from the owning lane. 4 lines/instruction instead of 32.
// ---------------------------------------------------------------------------
__global__ __launch_bounds__(128, 4)
void conv_h(const __half* __restrict__ src,
            const int*    __restrict__ idx,
            const float*  __restrict__ mask,
            const uint4*  __restrict__ Wf,
            float*        __restrict__ dst,
            float*        __restrict__ part)
{
    extern __shared__ char smraw[];
    char* smc = (char*)(((uintptr_t)smraw + 127) & ~(uintptr_t)127);
    uint32_t sb;
    asm("{ .reg .u64 t; cvta.to.shared.u64 t, %1; cvt.u32.u64 %0, t; }" : "=r"(sb) : "l"(smc));
    float* RED  = (float*)(smc + SM_RED);
    float* RED2 = (float*)(smc + SM_RED2);

    const int tid  = threadIdx.x;
    const int w    = tid >> 5;
    const int lane = tid & 31;
    const int n0   = blockIdx.x * TILE_M;
    const int n    = n0 + tid;            // row this lane OWNS (idx/mask)
    const int gq   = lane >> 2;
    const int tq   = lane & 3;
    const int mrow = lane & 7;
    const int mi   = lane >> 3;
    const int chk  = lane & 7;            // 16B chunk this lane copies
    const int rsub = lane >> 3;           // row-subgroup (0..3)

    // loop-invariant A LDSM addresses (relative; add stage base at use)
    uint32_t a_rel[4];
#pragma unroll
    for (int ks = 0; ks < 4; ++ks)
        a_rel[ks] = (uint32_t)(w * 32 + (mi & 1) * 8 + mrow) * 128u
                  + (uint32_t)((2 * ks + (mi >> 1)) ^ mrow) * 16u;

    // ---- prologue: issue A(0), A(1); prefetch idx/mask for A(2) ----
#pragma unroll
    for (int s = 0; s < 2; ++s) {
        int   gi_own = 0; float mm_own = 0.f;
        if (n < NP) { gi_own = idx[(size_t)s * NP + n]; mm_own = mask[(size_t)s * NP + n]; }
#pragma unroll
        for (int j = 0; j < 8; ++j) {
            const int rl = 4 * j + rsub;                    // row-local 0..31
            int   gi = __shfl_sync(0xFFFFFFFFu, gi_own, rl);
            float mm = __shfl_sync(0xFFFFFFFFu, mm_own, rl);
            const char* gp = (const char*)(src + (size_t)gi * CCH) + chk * 16;
            uint32_t sdst = sb + SM_AB(s) + (uint32_t)(w * 32 + rl) * 128u
                          + (uint32_t)((chk ^ (rl & 7)) * 16);
            CP_ASYNC_Z(sdst, gp, (mm != 0.f) ? 16u : 0u);
        }
        CP_COMMIT();
    }
    int   idx_c = 0;
    float m_c   = 0.f;
    if (n < NP) { idx_c = idx[(size_t)2 * NP + n]; m_c = mask[(size_t)2 * NP + n]; }

    float acc[2][8][4];
#pragma unroll
    for (int t = 0; t < 2; ++t)
#pragma unroll
        for (int nb = 0; nb < 8; ++nb)
#pragma unroll
            for (int i = 0; i < 4; ++i) acc[t][nb][i] = 0.f;

    for (int k = 0; k < KK; ++k) {
        CP_WAIT1();            // per-warp: A(k) resident (only A(k+1) may pend)
        __syncwarp();          // order async writes vs this warp's ldsm

        // ---- issue A(k+2) into stage (k+2)%3, divergence-free ----
        if (k + 2 < KK) {
#pragma unroll
            for (int j = 0; j < 8; ++j) {
                const int rl = 4 * j + rsub;
                int   gi = __shfl_sync(0xFFFFFFFFu, idx_c, rl);
                float mm = __shfl_sync(0xFFFFFFFFu, m_c, rl);
                const char* gp = (const char*)(src + (size_t)gi * CCH) + chk * 16;
                uint32_t sdst = sb + SM_AB(k + 2) + (uint32_t)(w * 32 + rl) * 128u
                              + (uint32_t)((chk ^ (rl & 7)) * 16);
                CP_ASYNC_Z(sdst, gp, (mm != 0.f) ? 16u : 0u);
            }
        }
        CP_COMMIT();
        idx_c = 0; m_c = 0.f;
        if (k + 3 < KK && n < NP) {
            idx_c = idx[(size_t)(k + 3) * NP + n];
            m_c   = mask[(size_t)(k + 3) * NP + n];
        }

        // ---- MMA: A via warp-local ldsm, B via fragment-order LDG.128 ----
        const uint32_t ab = sb + SM_AB(k);
        const uint4* wfk = Wf + (size_t)k * 512 + lane;
        uint4 ba = wfk[0];
        uint4 bb = wfk[32];
        uint32_t a00, a01, a02, a03, a10, a11, a12, a13;
#pragma unroll
        for (int i = 0; i < 16; ++i) {
            const int ks = i >> 2, nbp = i & 3;
            if (nbp == 0) {
                ldsm4(a00, a01, a02, a03, ab + a_rel[ks]);
                ldsm4(a10, a11, a12, a13, ab + a_rel[ks] + 2048u);
            }
            uint4 bc = ba;
            ba = bb;
            if (i + 2 < 16) bb = wfk[(size_t)(i + 2) * 32];
            mma16816(acc[0][2 * nbp],     a00, a01, a02, a03, bc.x, bc.y);
            mma16816(acc[0][2 * nbp + 1], a00, a01, a02, a03, bc.z, bc.w);
            mma16816(acc[1][2 * nbp],     a10, a11, a12, a13, bc.x, bc.y);
            mma16816(acc[1][2 * nbp + 1], a10, a11, a12, a13, bc.z, bc.w);
        }
    }

    // ---- epilogue: direct dst stores + shuffle-reduced BN partials ----
#pragma unroll
    for (int t = 0; t < 2; ++t) {
#pragma unroll
        for (int nb = 0; nb < 8; ++nb) {
            int rlo = n0 + w * 32 + t * 16 + gq;
            if (rlo < NP)
                *(float2*)(dst + (size_t)rlo * CCH + nb * 8 + 2 * tq) =
                    make_float2(acc[t][nb][0], acc[t][nb][1]);
            if (rlo + 8 < NP)
                *(float2*)(dst + (size_t)(rlo + 8) * CCH + nb * 8 + 2 * tq) =
                    make_float2(acc[t][nb][2], acc[t][nb][3]);
        }
    }
    // per-channel sums over this warp's 32 rows; rows >= NP hold exact zeros
#pragma unroll
    for (int cidx = 0; cidx < 16; ++cidx) {
        const int nb = cidx >> 1, j = cidx & 1;
        float p = acc[0][nb][j] + acc[0][nb][2 + j] + acc[1][nb][j] + acc[1][nb][2 + j];
        float q = acc[0][nb][j] * acc[0][nb][j];
        q = fmaf(acc[0][nb][2 + j], acc[0][nb][2 + j], q);
        q = fmaf(acc[1][nb][j],     acc[1][nb][j],     q);
        q = fmaf(acc[1][nb][2 + j], acc[1][nb][2 + j], q);
#pragma unroll
        for (int d = 4; d < 32; d <<= 1) {      // reduce over gq (lanes stride 4)
            p += __shfl_xor_sync(0xFFFFFFFFu, p, d);
            q += __shfl_xor_sync(0xFFFFFFFFu, q, d);
        }
        if (lane < 4) {                          // gq == 0
            RED[w * 64 + nb * 8 + 2 * tq + j]  = p;
            RED2[w * 64 + nb * 8 + 2 * tq + j] = q;
        }
    }
    __syncthreads();
    if (tid < CCH) {
        float s = 0.f, s2 = 0.f;
#pragma unroll
        for (int ww = 0; ww < 4; ++ww) { s += RED[ww * 64 + tid]; s2 += RED2[ww * 64 + tid]; }
        part[blockIdx.x * (2 * CCH) + tid]       = s;
        part[blockIdx.x * (2 * CCH) + CCH + tid] = s2;
    }
}

// ---------------------------------------------------------------------------
// prep: pack W[k][c][d] into mma-fragment order (lane = gq*4+tq, frag = ks*4+nbp)
// ---------------------------------------------------------------------------
__global__ __launch_bounds__(512)
void prep_wf(const float* __restrict__ W, uint4* __restrict__ Wf)
{
    const int k    = blockIdx.x;
    const int tid  = threadIdx.x;       // 512 = 16 frags x 32 lanes
    const int lane = tid & 31;
    const int f    = tid >> 5;
    const int ks   = f >> 2, nbp = f & 3;
    const int gq   = lane >> 2, tq = lane & 3;
    const int c0   = 16 * ks + 2 * tq;
    const int d0   = 16 * nbp + gq;
    const float* Wk = W + (size_t)k * CCH * CCH;
    union { __half2 h[4]; uint4 u; } o;
    o.h[0] = __floats2half2_rn(Wk[(c0 + 0) * CCH + d0],     Wk[(c0 + 1) * CCH + d0]);
    o.h[1] = __floats2half2_rn(Wk[(c0 + 8) * CCH + d0],     Wk[(c0 + 9) * CCH + d0]);
    o.h[2] = __floats2half2_rn(Wk[(c0 + 0) * CCH + d0 + 8], Wk[(c0 + 1) * CCH + d0 + 8]);
    o.h[3] = __floats2half2_rn(Wk[(c0 + 8) * CCH + d0 + 8], Wk[(c0 + 9) * CCH + d0 + 8]);
    Wf[(size_t)k * 512 + f * 32 + lane] = o.u;
}

// ---------------------------------------------------------------------------
// feats -> half  (8 elements / thread)
// ---------------------------------------------------------------------------
__global__ __launch_bounds__(256)
void f2h_kernel(const float* __restrict__ in, __half* __restrict__ out)
{
    int i = blockIdx.x * 256 + threadIdx.x;
    if (i < NP * CCH / 8) {
        const float4* p = (const float4*)in + 2 * i;
        float4 v0 = p[0], v1 = p[1];
        union { __half2 hh[4]; uint4 u; } cv;
        cv.hh[0] = __floats2half2_rn(v0.x, v0.y);
        cv.hh[1] = __floats2half2_rn(v0.z, v0.w);
        cv.hh[2] = __floats2half2_rn(v1.x, v1.y);
        cv.hh[3] = __floats2half2_rn(v1.z, v1.w);
        ((uint4*)out)[i] = cv.u;
    }
}

// ---------------------------------------------------------------------------
// h1 = half(relu(buf1*scale1 + shift1))   (8 elements / thread)
// ---------------------------------------------------------------------------
__global__ __launch_bounds__(256)
void bnrelu2h_kernel(const float* __restrict__ in, const float* __restrict__ stats,
                     __half* __restrict__ out)
{
    __shared__ float scsh[128];
    if (threadIdx.x < 128) scsh[threadIdx.x] = stats[threadIdx.x];
    __syncthreads();
    int i = blockIdx.x * 256 + threadIdx.x;
    if (i < NP * CCH / 8) {
        const float4* p = (const float4*)in + 2 * i;
        float4 v0 = p[0], v1 = p[1];
        int c0 = (i * 8) & 63;
        const float* sc = scsh, * sh = scsh + 64;
        float t[8];
        t[0] = fmaxf(fmaf(v0.x, sc[c0 + 0], sh[c0 + 0]), 0.f);
        t[1] = fmaxf(fmaf(v0.y, sc[c0 + 1], sh[c0 + 1]), 0.f);
        t[2] = fmaxf(fmaf(v0.z, sc[c0 + 2], sh[c0 + 2]), 0.f);
        t[3] = fmaxf(fmaf(v0.w, sc[c0 + 3], sh[c0 + 3]), 0.f);
        t[4] = fmaxf(fmaf(v1.x, sc[c0 + 4], sh[c0 + 4]), 0.f);
        t[5] = fmaxf(fmaf(v1.y, sc[c0 + 5], sh[c0 + 5]), 0.f);
        t[6] = fmaxf(fmaf(v1.z, sc[c0 + 6], sh[c0 + 6]), 0.f);
        t[7] = fmaxf(fmaf(v1.w, sc[c0 + 7], sh[c0 + 7]), 0.f);
        union { __half2 hh[4]; uint4 u; } cv;
        cv.hh[0] = __floats2half2_rn(t[0], t[1]);
        cv.hh[1] = __floats2half2_rn(t[2], t[3]);
        cv.hh[2] = __floats2half2_rn(t[4], t[5]);
        cv.hh[3] = __floats2half2_rn(t[6], t[7]);
        ((uint4*)out)[i] = cv.u;
    }
}

// ---------------------------------------------------------------------------
// Per-channel stats finalize: scale = gamma*rsqrt(var+eps), shift = beta - mean*scale
// ---------------------------------------------------------------------------
__global__ __launch_bounds__(256)
void finalize_kernel(const float* __restrict__ part,
                     const float* __restrict__ gamma,
                     const float* __restrict__ beta,
                     float*       __restrict__ stats)
{
    const int c   = blockIdx.x;
    const int tid = threadIdx.x;
    float s = 0.f, s2 = 0.f;
    for (int b = tid; b < NBC; b += 256) {
        s  += part[b * (2 * CCH) + c];
        s2 += part[b * (2 * CCH) + CCH + c];
    }
    __shared__ float r1[256], r2[256];
    r1[tid] = s; r2[tid] = s2;
    __syncthreads();
    for (int o = 128; o > 0; o >>= 1) {
        if (tid < o) { r1[tid] += r1[tid + o]; r2[tid] += r2[tid + o]; }
        __syncthreads();
    }
    if (tid == 0) {
        float mean = r1[0] * (1.0f / NP);
        float var  = r2[0] * (1.0f / NP) - mean * mean;
        float istd = rsqrtf(var + EPSV);
        float sc   = istd * gamma[c];
        stats[c]       = sc;
        stats[CCH + c] = beta[c] - mean * sc;
    }
}

// ---------------------------------------------------------------------------
// out = relu( buf2*scale2 + shift2 + feats )
// ---------------------------------------------------------------------------
__global__ __launch_bounds__(256)
void epi_kernel(const float* __restrict__ buf2,
                const float* __restrict__ stats,
                const float* __restrict__ feats,
                float*       __restrict__ out)
{
    __shared__ float sc[CCH], sh[CCH];
    if (threadIdx.x < CCH) {
        sc[threadIdx.x] = stats[threadIdx.x];
        sh[threadIdx.x] = stats[CCH + threadIdx.x];
    }
    __syncthreads();
    int i = blockIdx.x * blockDim.x + threadIdx.x;   // float4 index
    if (i < NP * CCH / 4) {
        float4 v = ((const float4*)buf2)[i];
        float4 f = ((const float4*)feats)[i];
        int c = (i * 4) & 63;
        v.x = fmaxf(fmaf(v.x, sc[c + 0], sh[c + 0]) + f.x, 0.f);
        v.y = fmaxf(fmaf(v.y, sc[c + 1], sh[c + 1]) + f.y, 0.f);
        v.z = fmaxf(fmaf(v.z, sc[c + 2], sh[c + 2]) + f.z, 0.f);
        v.w = fmaxf(fmaf(v.w, sc[c + 3], sh[c + 3]) + f.w, 0.f);
        ((float4*)out)[i] = v;
    }
}

// ---------------------------------------------------------------------------
extern "C" void kernel_launch(void* const* d_in, const int* in_sizes, int n_in,
                              void* d_out, int out_size)
{
    const float* feats  = (const float*)d_in[0];
    const float* W1     = (const float*)d_in[1];
    const float* gamma1 = (const float*)d_in[2];
    const float* beta1  = (const float*)d_in[3];
    const float* W2     = (const float*)d_in[4];
    const float* gamma2 = (const float*)d_in[5];
    const float* beta2  = (const float*)d_in[6];
    const int*   idx1   = (const int*)  d_in[7];
    const float* mask1  = (const float*)d_in[8];
    const int*   idx2   = (const int*)  d_in[9];
    const float* mask2  = (const float*)d_in[10];
    float* out = (float*)d_out;

    float *buf1, *buf2, *part1, *part2, *st1, *st2;
    __half *h0, *h1;
    uint4 *wf1, *wf2;
    cudaGetSymbolAddress((void**)&buf1,  g_buf1);
    cudaGetSymbolAddress((void**)&buf2,  g_buf2);
    cudaGetSymbolAddress((void**)&h0,    g_h0);
    cudaGetSymbolAddress((void**)&h1,    g_h1);
    cudaGetSymbolAddress((void**)&wf1,   g_wf1);
    cudaGetSymbolAddress((void**)&wf2,   g_wf2);
    cudaGetSymbolAddress((void**)&part1, g_part1);
    cudaGetSymbolAddress((void**)&part2, g_part2);
    cudaGetSymbolAddress((void**)&st1,   g_stats1);
    cudaGetSymbolAddress((void**)&st2,   g_stats2);

    cudaFuncSetAttribute(conv_h, cudaFuncAttributeMaxDynamicSharedMemorySize, SMEM_BYTES);

    const int cvt_blocks = (NP * CCH / 8 + 255) / 256;
    prep_wf<<<KK, 512>>>(W1, wf1);
    prep_wf<<<KK, 512>>>(W2, wf2);
    f2h_kernel<<<cvt_blocks, 256>>>(feats, h0);

    conv_h<<<NBC, 128, SMEM_BYTES>>>(h0, idx1, mask1, wf1, buf1, part1);
    finalize_kernel<<<CCH, 256>>>(part1, gamma1, beta1, st1);
    bnrelu2h_kernel<<<cvt_blocks, 256>>>(buf1, st1, h1);
    conv_h<<<NBC, 128, SMEM_BYTES>>>(h1, idx2, mask2, wf2, buf2, part2);
    finalize_kernel<<<CCH, 256>>>(part2, gamma2, beta2, st2);

    const int epi_blocks = (NP * CCH / 4 + 255) / 256;
    epi_kernel<<<epi_blocks, 256>>>(buf2, st2, feats, out);
}